// round 2
// baseline (speedup 1.0000x reference)
#include <cuda_runtime.h>
#include <math.h>

// Problem constants
#define BB 8192
#define PP 4096
#define DD 1024
#define LL 5
#define KK 5
#define EPSV 1e-8f

// ---------------- scratch (device globals: allocation-free) ----------------
__device__ float g_dot[(size_t)BB * PP];   // 128 MB score matrix (fp32, ~exact)
__device__ float g_xn[BB];
__device__ float g_kn[PP];
__device__ float g_rowloss[BB];
__device__ int   g_idx[BB * KK];

// ---------------- norms (double accumulation, rounded to fp32) ----------------
__global__ __launch_bounds__(256)
void norms_kernel(const float* __restrict__ x,
                  const float* __restrict__ keys) {
    int v = blockIdx.x;
    const float* src;
    float* dst;
    if (v < BB) { src = x + (size_t)v * DD;           dst = &g_xn[v]; }
    else        { src = keys + (size_t)(v - BB) * DD; dst = &g_kn[v - BB]; }

    double acc = 0.0;
    for (int d = threadIdx.x; d < DD; d += 256) {
        double t = (double)src[d];
        acc += t * t;
    }
    __shared__ double s[256];
    s[threadIdx.x] = acc;
    __syncthreads();
    for (int st = 128; st > 0; st >>= 1) {
        if (threadIdx.x < st) s[threadIdx.x] += s[threadIdx.x + st];
        __syncthreads();
    }
    if (threadIdx.x == 0) *dst = (float)sqrt(s[0]);
}

// ---------------- high-precision NT GEMM ----------------
// dot[b,p] = sum_d x[b,d]*keys[p,d]
// fp32 FMA in 8-term chunks, merged into double accumulators.
// Total error ~1.6e-8 absolute << fp32 ulp of the final value.
#define BM 128
#define BN 64
#define BK 8
#define TM 8
#define TN 4

__global__ __launch_bounds__(256)
void gemm_nt_kernel(const float* __restrict__ A,   // x: BB x DD
                    const float* __restrict__ Bm)  // keys: PP x DD
{
    __shared__ float As[BK][BM];   // 4 KB, k-major
    __shared__ float Bs[BK][BN];   // 2 KB, k-major

    const int bx = blockIdx.x;   // N tile (keys):  PP/BN = 64
    const int by = blockIdx.y;   // M tile (rows):  BB/BM = 64
    const int tid = threadIdx.x; // 256 threads

    const int trow = tid >> 4;         // 0..15  -> rows trow*8 .. +7
    const int tcol = tid & 15;         // 0..15  -> cols tcol*4 .. +3

    // global load mapping
    const int a_row  = tid >> 1;          // 0..127
    const int a_col4 = (tid & 1) * 4;     // 0 or 4
    const int b_row  = (tid & 127) >> 1;  // 0..63 (threads 0..127 load B)
    const int b_col4 = (tid & 1) * 4;

    const float* Aptr = A  + (size_t)(by * BM + a_row) * DD + a_col4;
    const float* Bptr = Bm + (size_t)(bx * BN + b_row) * DD + b_col4;

    double sum[TM][TN];
#pragma unroll
    for (int i = 0; i < TM; i++)
#pragma unroll
        for (int j = 0; j < TN; j++) sum[i][j] = 0.0;

    for (int k0 = 0; k0 < DD; k0 += BK) {
        float4 a4 = *(const float4*)(Aptr + k0);
        As[a_col4 + 0][a_row] = a4.x;
        As[a_col4 + 1][a_row] = a4.y;
        As[a_col4 + 2][a_row] = a4.z;
        As[a_col4 + 3][a_row] = a4.w;
        if (tid < 128) {
            float4 b4 = *(const float4*)(Bptr + k0);
            Bs[b_col4 + 0][b_row] = b4.x;
            Bs[b_col4 + 1][b_row] = b4.y;
            Bs[b_col4 + 2][b_row] = b4.z;
            Bs[b_col4 + 3][b_row] = b4.w;
        }
        __syncthreads();

        float chunk[TM][TN];
#pragma unroll
        for (int i = 0; i < TM; i++)
#pragma unroll
            for (int j = 0; j < TN; j++) chunk[i][j] = 0.f;

#pragma unroll
        for (int kk = 0; kk < BK; kk++) {
            float4 a0 = *(const float4*)&As[kk][trow * TM];
            float4 a1 = *(const float4*)&As[kk][trow * TM + 4];
            float4 b0 = *(const float4*)&Bs[kk][tcol * TN];
            float af[TM] = {a0.x, a0.y, a0.z, a0.w, a1.x, a1.y, a1.z, a1.w};
            float bf[TN] = {b0.x, b0.y, b0.z, b0.w};
#pragma unroll
            for (int i = 0; i < TM; i++)
#pragma unroll
                for (int j = 0; j < TN; j++)
                    chunk[i][j] = fmaf(af[i], bf[j], chunk[i][j]);
        }
        // exact merge of the 8-term chunk
#pragma unroll
        for (int i = 0; i < TM; i++)
#pragma unroll
            for (int j = 0; j < TN; j++)
                sum[i][j] += (double)chunk[i][j];
        __syncthreads();
    }

    const int row0 = by * BM + trow * TM;
    const int col0 = bx * BN + tcol * TN;
#pragma unroll
    for (int i = 0; i < TM; i++) {
        float4 v;
        v.x = (float)sum[i][0];
        v.y = (float)sum[i][1];
        v.z = (float)sum[i][2];
        v.w = (float)sum[i][3];
        *(float4*)&g_dot[(size_t)(row0 + i) * PP + col0] = v;
    }
}

// ---------------- top-5 per row, reference-exact ranking ----------------
// Rank by fp32 dist = 1 - cos (same quantization as jax), ties -> lowest index.
__device__ __forceinline__ unsigned int f32_ord(float f) {
    unsigned int b = __float_as_uint(f);
    return b ^ ((b & 0x80000000u) ? 0xFFFFFFFFu : 0x80000000u);
}
__device__ __forceinline__ float ord_f32(unsigned int o) {
    unsigned int b = o ^ ((o & 0x80000000u) ? 0x80000000u : 0xFFFFFFFFu);
    return __uint_as_float(b);
}

__global__ __launch_bounds__(256)
void topk_kernel() {
    const int b = blockIdx.x;
    const int tid = threadIdx.x;
    __shared__ unsigned int s_ord[PP];            // 16 KB
    __shared__ unsigned long long s_red[8];       // per-warp partials

    const float xnb = g_xn[b];
    const float* drow = &g_dot[(size_t)b * PP];
    for (int p = tid; p < PP; p += 256) {
        float denom = fmaxf(xnb * g_kn[p], EPSV);
        float cosv  = __fdiv_rn(drow[p], denom);   // IEEE fp32 division, like jax
        float dist  = 1.0f - cosv;                 // fp32 quantization, like jax
        s_ord[p] = f32_ord(dist);
    }
    __syncthreads();

    float loss = 0.f;
    const int lane = tid & 31;
    const int warp = tid >> 5;

    for (int k = 0; k < KK; k++) {
        unsigned long long best = 0xFFFFFFFFFFFFFFFFull;
        for (int p = tid; p < PP; p += 256) {
            unsigned long long key = ((unsigned long long)s_ord[p] << 32) | (unsigned int)p;
            best = min(best, key);
        }
#pragma unroll
        for (int st = 16; st > 0; st >>= 1)
            best = min(best, __shfl_xor_sync(0xFFFFFFFFu, best, st));
        if (lane == 0) s_red[warp] = best;
        __syncthreads();
        if (warp == 0) {
            unsigned long long v = (lane < 8) ? s_red[lane] : 0xFFFFFFFFFFFFFFFFull;
#pragma unroll
            for (int st = 4; st > 0; st >>= 1)
                v = min(v, __shfl_xor_sync(0xFFFFFFFFu, v, st));
            if (lane == 0) s_red[0] = v;
        }
        __syncthreads();
        unsigned long long win = s_red[0];
        int sel = (int)(win & 0xFFFFFFFFu);
        if (tid == 0) {
            g_idx[b * KK + k] = sel;
            loss += ord_f32((unsigned int)(win >> 32));
            s_ord[sel] = 0xFFFFFFFFu;   // remove winner
        }
        __syncthreads();
    }
    if (tid == 0) g_rowloss[b] = loss;
}

// ---------------- deterministic loss reduction ----------------
__global__ __launch_bounds__(256)
void loss_reduce_kernel(float* __restrict__ out, int out_size) {
    __shared__ double s[256];
    int tid = threadIdx.x;
    double acc = 0.0;
    for (int i = tid; i < BB; i += 256) acc += (double)g_rowloss[i];
    s[tid] = acc;
    __syncthreads();
    for (int st = 128; st > 0; st >>= 1) {
        if (tid < st) s[tid] += s[tid + st];
        __syncthreads();
    }
    if (tid == 0) out[out_size - 1] = (float)(s[0] / (double)(BB * KK));
}

// ---------------- gather: out[b, k*L+l, :] = values[idx[b,k], l, :] ----------------
__global__ __launch_bounds__(256)
void gather_kernel(const float* __restrict__ values, float* __restrict__ out) {
    const long long total = (long long)BB * (KK * LL) * (DD / 4);   // 52,428,800 float4s
    long long gid = (long long)blockIdx.x * 256 + threadIdx.x;
    if (gid >= total) return;
    int b  = (int)(gid / 6400);
    int r  = (int)(gid % 6400);
    int j  = r >> 8;        // 0..24
    int d4 = r & 255;       // 0..255
    int k = j / LL;
    int l = j - k * LL;
    int p = g_idx[b * KK + k];
    float4 v = ((const float4*)values)[((size_t)p * LL + l) * (DD / 4) + d4];
    ((float4*)out)[gid] = v;
}

// ---------------- launch ----------------
extern "C" void kernel_launch(void* const* d_in, const int* in_sizes, int n_in,
                              void* d_out, int out_size) {
    const float* x      = (const float*)d_in[0];   // (B,1,D)
    const float* keys   = (const float*)d_in[1];   // (P,D)
    const float* values = (const float*)d_in[2];   // (P,L,D)
    float* out = (float*)d_out;

    norms_kernel<<<BB + PP, 256>>>(x, keys);

    dim3 gg(PP / BN, BB / BM);
    gemm_nt_kernel<<<gg, 256>>>(x, keys);

    topk_kernel<<<BB, 256>>>();

    loss_reduce_kernel<<<1, 256>>>(out, out_size);

    const long long total4 = (long long)BB * (KK * LL) * (DD / 4);
    int gblocks = (int)((total4 + 255) / 256);
    gather_kernel<<<gblocks, 256>>>(values, out);
}

// round 3
// speedup vs baseline: 7.4685x; 7.4685x over previous
#include <cuda_runtime.h>
#include <math.h>

// Problem constants
#define BB 8192
#define PP 4096
#define DD 1024
#define LL 5
#define KK 5
#define EPSV 1e-8f

// Candidate margin (dist units). Max approx-GEMM dist error ~3e-6; 100x safety.
#define DELTA 3e-4f
#define CMAX 256

// ---------------- scratch (device globals: allocation-free) ----------------
__device__ float g_dot[(size_t)BB * PP];   // 128 MB approx score matrix
__device__ float g_xn[BB];
__device__ float g_kn[PP];
__device__ float g_rowloss[BB];
__device__ int   g_idx[BB * KK];

// ---------------- norms (double accumulation, rounded to fp32) ----------------
__global__ __launch_bounds__(256)
void norms_kernel(const float* __restrict__ x,
                  const float* __restrict__ keys) {
    int v = blockIdx.x;
    const float* src;
    float* dst;
    if (v < BB) { src = x + (size_t)v * DD;           dst = &g_xn[v]; }
    else        { src = keys + (size_t)(v - BB) * DD; dst = &g_kn[v - BB]; }

    double acc = 0.0;
    for (int d = threadIdx.x; d < DD; d += 256) {
        double t = (double)src[d];
        acc += t * t;
    }
    __shared__ double s[256];
    s[threadIdx.x] = acc;
    __syncthreads();
    for (int st = 128; st > 0; st >>= 1) {
        if (threadIdx.x < st) s[threadIdx.x] += s[threadIdx.x + st];
        __syncthreads();
    }
    if (threadIdx.x == 0) *dst = (float)sqrt(s[0]);
}

// ---------------- fast fp32 NT GEMM (approximate scores) ----------------
#define BM 128
#define BN 128
#define BKG 8
#define TM 8
#define TN 8

__global__ __launch_bounds__(256, 2)
void gemm_nt_kernel(const float* __restrict__ A,   // x: BB x DD
                    const float* __restrict__ Bm)  // keys: PP x DD
{
    __shared__ float As[2][BKG][BM];   // 8 KB
    __shared__ float Bs[2][BKG][BN];   // 8 KB

    const int bx = blockIdx.x;   // N tile: PP/BN = 32
    const int by = blockIdx.y;   // M tile: BB/BM = 64
    const int tid = threadIdx.x;

    const int trow = tid >> 4;         // 0..15
    const int tcol = tid & 15;         // 0..15

    const int g_row  = tid >> 1;       // 0..127
    const int g_col4 = (tid & 1) * 4;  // 0 or 4

    const float* Aptr = A  + (size_t)(by * BM + g_row) * DD + g_col4;
    const float* Bptr = Bm + (size_t)(bx * BN + g_row) * DD + g_col4;

    float acc[TM][TN];
#pragma unroll
    for (int i = 0; i < TM; i++)
#pragma unroll
        for (int j = 0; j < TN; j++) acc[i][j] = 0.f;

    // prologue: stage 0
    {
        float4 a4 = *(const float4*)(Aptr);
        float4 b4 = *(const float4*)(Bptr);
        As[0][g_col4 + 0][g_row] = a4.x; As[0][g_col4 + 1][g_row] = a4.y;
        As[0][g_col4 + 2][g_row] = a4.z; As[0][g_col4 + 3][g_row] = a4.w;
        Bs[0][g_col4 + 0][g_row] = b4.x; Bs[0][g_col4 + 1][g_row] = b4.y;
        Bs[0][g_col4 + 2][g_row] = b4.z; Bs[0][g_col4 + 3][g_row] = b4.w;
    }
    __syncthreads();

    int buf = 0;
    for (int k0 = 0; k0 < DD; k0 += BKG) {
        const int nk = k0 + BKG;
        float4 a4n, b4n;
        if (nk < DD) {
            a4n = *(const float4*)(Aptr + nk);
            b4n = *(const float4*)(Bptr + nk);
        }

#pragma unroll
        for (int kk = 0; kk < BKG; kk++) {
            float4 a0 = *(const float4*)&As[buf][kk][trow * TM];
            float4 a1 = *(const float4*)&As[buf][kk][trow * TM + 4];
            float4 b0 = *(const float4*)&Bs[buf][kk][tcol * TN];
            float4 b1 = *(const float4*)&Bs[buf][kk][tcol * TN + 4];
            float af[TM] = {a0.x, a0.y, a0.z, a0.w, a1.x, a1.y, a1.z, a1.w};
            float bf[TN] = {b0.x, b0.y, b0.z, b0.w, b1.x, b1.y, b1.z, b1.w};
#pragma unroll
            for (int i = 0; i < TM; i++)
#pragma unroll
                for (int j = 0; j < TN; j++)
                    acc[i][j] = fmaf(af[i], bf[j], acc[i][j]);
        }

        if (nk < DD) {
            const int nb = buf ^ 1;
            As[nb][g_col4 + 0][g_row] = a4n.x; As[nb][g_col4 + 1][g_row] = a4n.y;
            As[nb][g_col4 + 2][g_row] = a4n.z; As[nb][g_col4 + 3][g_row] = a4n.w;
            Bs[nb][g_col4 + 0][g_row] = b4n.x; Bs[nb][g_col4 + 1][g_row] = b4n.y;
            Bs[nb][g_col4 + 2][g_row] = b4n.z; Bs[nb][g_col4 + 3][g_row] = b4n.w;
            __syncthreads();
            buf = nb;
        }
    }

    const int row0 = by * BM + trow * TM;
    const int col0 = bx * BN + tcol * TN;
#pragma unroll
    for (int i = 0; i < TM; i++) {
        float4 v0, v1;
        v0.x = acc[i][0]; v0.y = acc[i][1]; v0.z = acc[i][2]; v0.w = acc[i][3];
        v1.x = acc[i][4]; v1.y = acc[i][5]; v1.z = acc[i][6]; v1.w = acc[i][7];
        *(float4*)&g_dot[(size_t)(row0 + i) * PP + col0]     = v0;
        *(float4*)&g_dot[(size_t)(row0 + i) * PP + col0 + 4] = v1;
    }
}

// ---------------- ordered-float helpers ----------------
__device__ __forceinline__ unsigned int f32_ord(float f) {
    unsigned int b = __float_as_uint(f);
    return b ^ ((b & 0x80000000u) ? 0xFFFFFFFFu : 0x80000000u);
}
__device__ __forceinline__ float ord_f32(unsigned int o) {
    unsigned int b = o ^ ((o & 0x80000000u) ? 0x80000000u : 0xFFFFFFFFu);
    return __uint_as_float(b);
}

// ---------------- top-5: approx select + margin + exact rescore ----------------
__global__ __launch_bounds__(256)
void topk_kernel(const float* __restrict__ x, const float* __restrict__ keys) {
    const int b = blockIdx.x;
    const int tid = threadIdx.x;
    const int lane = tid & 31;
    const int warp = tid >> 5;

    __shared__ unsigned int s_ord[PP];              // 16 KB approx dist (ordered)
    __shared__ float s_x[DD];                       // 4 KB row of x
    __shared__ unsigned long long s_key[CMAX];      // candidate (ord<<32)|p
    __shared__ unsigned long long s_red[8];
    __shared__ int s_cnt;

    const float xnb = g_xn[b];
    const float* drow = &g_dot[(size_t)b * PP];
    for (int p = tid; p < PP; p += 256) {
        float denom = fmaxf(xnb * g_kn[p], EPSV);
        float dist = 1.0f - __fdiv_rn(drow[p], denom);
        s_ord[p] = f32_ord(dist);
    }
    for (int d = tid; d < DD; d += 256) s_x[d] = x[(size_t)b * DD + d];
    if (tid == 0) s_cnt = KK;   // slots 0..4 reserved for the 5 approx winners
    __syncthreads();

    // ---- 5 approx argmin passes; winners recorded, removed from s_ord ----
    unsigned int T_ord = 0;   // ord of approx 5th-smallest (max of winners)
    for (int k = 0; k < KK; k++) {
        unsigned long long best = 0xFFFFFFFFFFFFFFFFull;
        for (int p = tid; p < PP; p += 256) {
            unsigned long long key = ((unsigned long long)s_ord[p] << 32) | (unsigned int)p;
            best = min(best, key);
        }
#pragma unroll
        for (int st = 16; st > 0; st >>= 1)
            best = min(best, __shfl_xor_sync(0xFFFFFFFFu, best, st));
        if (lane == 0) s_red[warp] = best;
        __syncthreads();
        if (warp == 0) {
            unsigned long long v = (lane < 8) ? s_red[lane] : 0xFFFFFFFFFFFFFFFFull;
#pragma unroll
            for (int st = 4; st > 0; st >>= 1)
                v = min(v, __shfl_xor_sync(0xFFFFFFFFu, v, st));
            if (lane == 0) s_red[0] = v;
        }
        __syncthreads();
        unsigned long long win = s_red[0];
        if (tid == 0) {
            s_key[k] = win;                       // approx winner is a candidate
            s_ord[(unsigned int)(win & 0xFFFFFFFFu)] = 0xFFFFFFFFu;
        }
        T_ord = (unsigned int)(win >> 32);        // last pass = 5th smallest
        __syncthreads();
    }

    // ---- margin scan: all remaining keys with dist <= T + DELTA ----
    const unsigned int th_ord = f32_ord(ord_f32(T_ord) + DELTA);
    for (int p = tid; p < PP; p += 256) {
        unsigned int o = s_ord[p];
        if (o <= th_ord) {
            int pos = atomicAdd(&s_cnt, 1);
            if (pos < CMAX)
                s_key[pos] = ((unsigned long long)o << 32) | (unsigned int)p;
        }
    }
    __syncthreads();
    const int cnt = min(s_cnt, CMAX);

    // ---- exact rescore of candidates: fp64 dot, fp32-quantized dist ----
    for (int c = warp; c < cnt; c += 8) {
        const int p = (int)(s_key[c] & 0xFFFFFFFFu);
        const float* krow = keys + (size_t)p * DD;
        double acc = 0.0;
        for (int d = lane; d < DD; d += 32)
            acc += (double)s_x[d] * (double)krow[d];
#pragma unroll
        for (int st = 16; st > 0; st >>= 1)
            acc += __shfl_xor_sync(0xFFFFFFFFu, acc, st);
        if (lane == 0) {
            float dotf  = (float)acc;
            float denom = fmaxf(xnb * g_kn[p], EPSV);
            float dist  = 1.0f - __fdiv_rn(dotf, denom);
            s_key[c] = ((unsigned long long)f32_ord(dist) << 32) | (unsigned int)p;
        }
    }
    __syncthreads();

    // ---- exact top-5 among candidates ----
    double loss = 0.0;
    for (int k = 0; k < KK; k++) {
        unsigned long long best = (tid < cnt) ? s_key[tid] : 0xFFFFFFFFFFFFFFFFull;
#pragma unroll
        for (int st = 16; st > 0; st >>= 1)
            best = min(best, __shfl_xor_sync(0xFFFFFFFFu, best, st));
        if (lane == 0) s_red[warp] = best;
        __syncthreads();
        if (warp == 0) {
            unsigned long long v = (lane < 8) ? s_red[lane] : 0xFFFFFFFFFFFFFFFFull;
#pragma unroll
            for (int st = 4; st > 0; st >>= 1)
                v = min(v, __shfl_xor_sync(0xFFFFFFFFu, v, st));
            if (lane == 0) s_red[0] = v;
        }
        __syncthreads();
        unsigned long long win = s_red[0];
        if (tid < cnt && s_key[tid] == win) s_key[tid] = 0xFFFFFFFFFFFFFFFFull;
        if (tid == 0) {
            g_idx[b * KK + k] = (int)(win & 0xFFFFFFFFu);
            loss += (double)ord_f32((unsigned int)(win >> 32));
        }
        __syncthreads();
    }
    if (tid == 0) g_rowloss[b] = (float)loss;
}

// ---------------- deterministic loss reduction ----------------
__global__ __launch_bounds__(256)
void loss_reduce_kernel(float* __restrict__ out, int out_size) {
    __shared__ double s[256];
    int tid = threadIdx.x;
    double acc = 0.0;
    for (int i = tid; i < BB; i += 256) acc += (double)g_rowloss[i];
    s[tid] = acc;
    __syncthreads();
    for (int st = 128; st > 0; st >>= 1) {
        if (tid < st) s[tid] += s[tid + st];
        __syncthreads();
    }
    if (tid == 0) out[out_size - 1] = (float)(s[0] / (double)(BB * KK));
}

// ---------------- gather: out[b, k*L+l, :] = values[idx[b,k], l, :] ----------------
__global__ __launch_bounds__(256)
void gather_kernel(const float* __restrict__ values, float* __restrict__ out) {
    const long long total = (long long)BB * (KK * LL) * (DD / 4);   // 52,428,800 float4s
    long long gid = (long long)blockIdx.x * 256 + threadIdx.x;
    if (gid >= total) return;
    int b  = (int)(gid / 6400);
    int r  = (int)(gid % 6400);
    int j  = r >> 8;        // 0..24
    int d4 = r & 255;       // 0..255
    int k = j / LL;
    int l = j - k * LL;
    int p = g_idx[b * KK + k];
    float4 v = ((const float4*)values)[((size_t)p * LL + l) * (DD / 4) + d4];
    ((float4*)out)[gid] = v;
}

// ---------------- launch ----------------
extern "C" void kernel_launch(void* const* d_in, const int* in_sizes, int n_in,
                              void* d_out, int out_size) {
    const float* x      = (const float*)d_in[0];   // (B,1,D)
    const float* keys   = (const float*)d_in[1];   // (P,D)
    const float* values = (const float*)d_in[2];   // (P,L,D)
    float* out = (float*)d_out;

    norms_kernel<<<BB + PP, 256>>>(x, keys);

    dim3 gg(PP / BN, BB / BM);
    gemm_nt_kernel<<<gg, 256>>>(x, keys);

    topk_kernel<<<BB, 256>>>(x, keys);

    loss_reduce_kernel<<<1, 256>>>(out, out_size);

    const long long total4 = (long long)BB * (KK * LL) * (DD / 4);
    int gblocks = (int)((total4 + 255) / 256);
    gather_kernel<<<gblocks, 256>>>(values, out);
}

// round 6
// speedup vs baseline: 11.5529x; 1.5469x over previous
#include <cuda_runtime.h>
#include <cuda_bf16.h>
#include <math.h>
#include <stdint.h>

// Problem constants
#define BB 8192
#define PP 4096
#define DD 1024
#define LL 5
#define KK 5
#define EPSV 1e-8f

// Candidate margin (dist units). bf16-split GEMM dist error ~1e-6; huge safety.
#define DELTA 3e-4f
#define CMAX 256

// GEMM config
#define KSPLIT 3072          // 3 segments of 1024: [hi,hi,lo] x [k_hi,k_lo,k_hi]
#define BKC 32               // k per chunk (bf16)
#define NCH (KSPLIT / BKC)   // 96 chunks
#define ROWB 80              // padded smem row bytes (32 bf16 = 64B data + 16B pad)
#define STAGE_BYTES (128 * ROWB * 2)   // A tile + B tile = 20480

// ---------------- scratch (device globals: allocation-free) ----------------
__device__ float g_dot[(size_t)BB * PP];                    // 128 MB approx scores
__device__ __nv_bfloat16 g_A[(size_t)BB * KSPLIT];          // 48 MB  [hi, hi, lo]
__device__ __nv_bfloat16 g_Bk[(size_t)PP * KSPLIT];         // 24 MB  [k_hi, k_lo, k_hi]
__device__ float g_xn[BB];
__device__ float g_kn[PP];
__device__ float g_rowloss[BB];
__device__ int   g_idx[BB * KK];

// ================= helpers =================
__device__ __forceinline__ uint32_t smem_to_u32(const void* p) {
    uint32_t a;
    asm("{ .reg .u64 t; cvta.to.shared.u64 t, %1; cvt.u32.u64 %0, t; }" : "=r"(a) : "l"(p));
    return a;
}
__device__ __forceinline__ void cp16(uint32_t dst, const void* src) {
    asm volatile("cp.async.cg.shared.global [%0], [%1], 16;" :: "r"(dst), "l"(src) : "memory");
}
__device__ __forceinline__ void ldsm_x4(uint32_t (&r)[4], uint32_t addr) {
    asm volatile("ldmatrix.sync.aligned.m8n8.x4.shared.b16 {%0,%1,%2,%3}, [%4];"
        : "=r"(r[0]), "=r"(r[1]), "=r"(r[2]), "=r"(r[3]) : "r"(addr));
}
__device__ __forceinline__ void mma16816(float (&c)[4], const uint32_t (&a)[4],
                                         uint32_t b0, uint32_t b1) {
    asm volatile("mma.sync.aligned.m16n8k16.row.col.f32.bf16.bf16.f32 "
        "{%0,%1,%2,%3}, {%4,%5,%6,%7}, {%8,%9}, {%0,%1,%2,%3};"
        : "+f"(c[0]), "+f"(c[1]), "+f"(c[2]), "+f"(c[3])
        : "r"(a[0]), "r"(a[1]), "r"(a[2]), "r"(a[3]), "r"(b0), "r"(b1));
}

// ---------------- norms (double accumulation, rounded to fp32) ----------------
__global__ __launch_bounds__(256)
void norms_kernel(const float* __restrict__ x,
                  const float* __restrict__ keys) {
    int v = blockIdx.x;
    const float* src;
    float* dst;
    if (v < BB) { src = x + (size_t)v * DD;           dst = &g_xn[v]; }
    else        { src = keys + (size_t)(v - BB) * DD; dst = &g_kn[v - BB]; }

    double acc = 0.0;
    for (int d = threadIdx.x; d < DD; d += 256) {
        double t = (double)src[d];
        acc += t * t;
    }
    __shared__ double s[256];
    s[threadIdx.x] = acc;
    __syncthreads();
    for (int st = 128; st > 0; st >>= 1) {
        if (threadIdx.x < st) s[threadIdx.x] += s[threadIdx.x + st];
        __syncthreads();
    }
    if (threadIdx.x == 0) *dst = (float)sqrt(s[0]);
}

// ---------------- bf16 hi/lo split packers ----------------
__global__ __launch_bounds__(256)
void split_x_kernel(const float* __restrict__ x) {
    int b = blockIdx.x;
    const float* row = x + (size_t)b * DD;
    __nv_bfloat16* dst = g_A + (size_t)b * KSPLIT;
    for (int d = threadIdx.x; d < DD; d += 256) {
        float f = row[d];
        __nv_bfloat16 hi = __float2bfloat16_rn(f);
        __nv_bfloat16 lo = __float2bfloat16_rn(f - __bfloat162float(hi));
        dst[d]          = hi;
        dst[DD + d]     = hi;
        dst[2 * DD + d] = lo;
    }
}
__global__ __launch_bounds__(256)
void split_k_kernel(const float* __restrict__ keys) {
    int p = blockIdx.x;
    const float* row = keys + (size_t)p * DD;
    __nv_bfloat16* dst = g_Bk + (size_t)p * KSPLIT;
    for (int d = threadIdx.x; d < DD; d += 256) {
        float f = row[d];
        __nv_bfloat16 hi = __float2bfloat16_rn(f);
        __nv_bfloat16 lo = __float2bfloat16_rn(f - __bfloat162float(hi));
        dst[d]          = hi;
        dst[DD + d]     = lo;
        dst[2 * DD + d] = hi;
    }
}

// ---------------- mma.sync bf16 GEMM: 128x128 tile, K=3072 ----------------
// g_dot[m, n] = sum_k g_A[m, k] * g_Bk[n, k]
__global__ __launch_bounds__(256, 2)
void gemm_mma_kernel() {
    __shared__ __align__(16) char smem[2 * STAGE_BYTES];   // 40 KB
    const uint32_t sb = smem_to_u32(smem);

    const int tid  = threadIdx.x;
    const int wid  = tid >> 5;
    const int lane = tid & 31;
    const int wm = wid >> 2;       // 0..1  -> M offset wm*64
    const int wn = wid & 3;        // 0..3  -> N offset wn*32
    const int bx = blockIdx.x;     // N tile: PP/128 = 32
    const int by = blockIdx.y;     // M tile: BB/128 = 64

    const __nv_bfloat16* Abase = g_A  + (size_t)(by * 128) * KSPLIT;
    const __nv_bfloat16* Bbase = g_Bk + (size_t)(bx * 128) * KSPLIT;

    // per-stage layout: A at +0 (128 rows x 80B), B at +10240 (128 rows x 80B)
    auto load_chunk = [&](int c, int st) {
        const uint32_t base = sb + st * STAGE_BYTES;
#pragma unroll
        for (int i = 0; i < 2; i++) {          // A: ids 0..511
            int id = tid + i * 256;
            int r = id >> 2, s = id & 3;
            cp16(base + r * ROWB + s * 16,
                 Abase + (size_t)r * KSPLIT + c * BKC + s * 8);
        }
#pragma unroll
        for (int i = 0; i < 2; i++) {          // B: ids 0..511
            int id = tid + i * 256;
            int r = id >> 2, s = id & 3;
            cp16(base + 10240 + r * ROWB + s * 16,
                 Bbase + (size_t)r * KSPLIT + c * BKC + s * 8);
        }
        asm volatile("cp.async.commit_group;" ::: "memory");
    };

    float acc[4][4][4];
#pragma unroll
    for (int i = 0; i < 4; i++)
#pragma unroll
        for (int j = 0; j < 4; j++)
#pragma unroll
            for (int q = 0; q < 4; q++) acc[i][j][q] = 0.f;

    load_chunk(0, 0);
    load_chunk(1, 1);

    // ldmatrix source rows for this lane
    const int lr  = lane & 15;          // row within 16-row tile
    const int lkh = (lane >> 4) * 16;   // 0 or 16 bytes (k-half)

    for (int c = 0; c < NCH; c++) {
        const int st = c & 1;
        if (c < NCH - 2) asm volatile("cp.async.wait_group 1;" ::: "memory");
        else             asm volatile("cp.async.wait_group 0;" ::: "memory");
        __syncthreads();

        const uint32_t aB = sb + st * STAGE_BYTES;
        const uint32_t bB = aB + 10240;

#pragma unroll
        for (int ks = 0; ks < 2; ks++) {       // two k16 steps per 32-chunk
            const int kb = ks * 32;            // byte offset of k16 within row
            uint32_t a[4][4];
#pragma unroll
            for (int mi = 0; mi < 4; mi++)
                ldsm_x4(a[mi], aB + (wm * 64 + mi * 16 + lr) * ROWB + kb + lkh);
            uint32_t bt[2][4];
#pragma unroll
            for (int nt = 0; nt < 2; nt++)
                ldsm_x4(bt[nt], bB + (wn * 32 + nt * 16 + lr) * ROWB + kb + lkh);
#pragma unroll
            for (int mi = 0; mi < 4; mi++)
#pragma unroll
                for (int ni = 0; ni < 4; ni++) {
                    const int nt = ni >> 1, hi = ni & 1;
                    mma16816(acc[mi][ni], a[mi], bt[nt][hi], bt[nt][hi + 2]);
                }
        }
        __syncthreads();
        if (c + 2 < NCH) load_chunk(c + 2, st);
    }

    // epilogue: direct float2 stores
    const int g  = lane >> 2;
    const int t2 = (lane & 3) * 2;
    const size_t rowbase = (size_t)(by * 128 + wm * 64);
    const int colbase = bx * 128 + wn * 32;
#pragma unroll
    for (int mi = 0; mi < 4; mi++)
#pragma unroll
        for (int ni = 0; ni < 4; ni++) {
            size_t r0 = rowbase + mi * 16 + g;
            int col = colbase + ni * 8 + t2;
            float2 v0 = make_float2(acc[mi][ni][0], acc[mi][ni][1]);
            float2 v1 = make_float2(acc[mi][ni][2], acc[mi][ni][3]);
            *(float2*)&g_dot[r0 * PP + col]       = v0;
            *(float2*)&g_dot[(r0 + 8) * PP + col] = v1;
        }
}

// ---------------- ordered-float helpers ----------------
__device__ __forceinline__ unsigned int f32_ord(float f) {
    unsigned int b = __float_as_uint(f);
    return b ^ ((b & 0x80000000u) ? 0xFFFFFFFFu : 0x80000000u);
}
__device__ __forceinline__ float ord_f32(unsigned int o) {
    unsigned int b = o ^ ((o & 0x80000000u) ? 0x80000000u : 0xFFFFFFFFu);
    return __uint_as_float(b);
}

// ---------------- top-5: approx select + margin + exact rescore ----------------
__global__ __launch_bounds__(256)
void topk_kernel(const float* __restrict__ x, const float* __restrict__ keys) {
    const int b = blockIdx.x;
    const int tid = threadIdx.x;
    const int lane = tid & 31;
    const int warp = tid >> 5;

    __shared__ unsigned int s_ord[PP];              // 16 KB approx dist (ordered)
    __shared__ float s_x[DD];                       // 4 KB row of x
    __shared__ unsigned long long s_key[CMAX];      // candidate (ord<<32)|p
    __shared__ unsigned long long s_red[8];
    __shared__ int s_cnt;

    const float xnb = g_xn[b];
    const float* drow = &g_dot[(size_t)b * PP];
    for (int p = tid; p < PP; p += 256) {
        float denom = fmaxf(xnb * g_kn[p], EPSV);
        float dist = 1.0f - __fdiv_rn(drow[p], denom);
        s_ord[p] = f32_ord(dist);
    }
    for (int d = tid; d < DD; d += 256) s_x[d] = x[(size_t)b * DD + d];
    if (tid == 0) s_cnt = KK;
    __syncthreads();

    // ---- 5 approx argmin passes ----
    unsigned int T_ord = 0;
    for (int k = 0; k < KK; k++) {
        unsigned long long best = 0xFFFFFFFFFFFFFFFFull;
        for (int p = tid; p < PP; p += 256) {
            unsigned long long key = ((unsigned long long)s_ord[p] << 32) | (unsigned int)p;
            best = min(best, key);
        }
#pragma unroll
        for (int st = 16; st > 0; st >>= 1)
            best = min(best, __shfl_xor_sync(0xFFFFFFFFu, best, st));
        if (lane == 0) s_red[warp] = best;
        __syncthreads();
        if (warp == 0) {
            unsigned long long v = (lane < 8) ? s_red[lane] : 0xFFFFFFFFFFFFFFFFull;
#pragma unroll
            for (int st = 4; st > 0; st >>= 1)
                v = min(v, __shfl_xor_sync(0xFFFFFFFFu, v, st));
            if (lane == 0) s_red[0] = v;
        }
        __syncthreads();
        unsigned long long win = s_red[0];
        if (tid == 0) {
            s_key[k] = win;
            s_ord[(unsigned int)(win & 0xFFFFFFFFu)] = 0xFFFFFFFFu;
        }
        T_ord = (unsigned int)(win >> 32);
        __syncthreads();
    }

    // ---- margin scan ----
    const unsigned int th_ord = f32_ord(ord_f32(T_ord) + DELTA);
    for (int p = tid; p < PP; p += 256) {
        unsigned int o = s_ord[p];
        if (o <= th_ord) {
            int pos = atomicAdd(&s_cnt, 1);
            if (pos < CMAX)
                s_key[pos] = ((unsigned long long)o << 32) | (unsigned int)p;
        }
    }
    __syncthreads();
    const int cnt = min(s_cnt, CMAX);

    // ---- exact rescore: fp64 dot, fp32-quantized dist ----
    for (int c = warp; c < cnt; c += 8) {
        const int p = (int)(s_key[c] & 0xFFFFFFFFu);
        const float* krow = keys + (size_t)p * DD;
        double acc = 0.0;
        for (int d = lane; d < DD; d += 32)
            acc += (double)s_x[d] * (double)krow[d];
#pragma unroll
        for (int st = 16; st > 0; st >>= 1)
            acc += __shfl_xor_sync(0xFFFFFFFFu, acc, st);
        if (lane == 0) {
            float dotf  = (float)acc;
            float denom = fmaxf(xnb * g_kn[p], EPSV);
            float dist  = 1.0f - __fdiv_rn(dotf, denom);
            s_key[c] = ((unsigned long long)f32_ord(dist) << 32) | (unsigned int)p;
        }
    }
    __syncthreads();

    // ---- exact top-5 among candidates ----
    double loss = 0.0;
    for (int k = 0; k < KK; k++) {
        unsigned long long best = (tid < cnt) ? s_key[tid] : 0xFFFFFFFFFFFFFFFFull;
#pragma unroll
        for (int st = 16; st > 0; st >>= 1)
            best = min(best, __shfl_xor_sync(0xFFFFFFFFu, best, st));
        if (lane == 0) s_red[warp] = best;
        __syncthreads();
        if (warp == 0) {
            unsigned long long v = (lane < 8) ? s_red[lane] : 0xFFFFFFFFFFFFFFFFull;
#pragma unroll
            for (int st = 4; st > 0; st >>= 1)
                v = min(v, __shfl_xor_sync(0xFFFFFFFFu, v, st));
            if (lane == 0) s_red[0] = v;
        }
        __syncthreads();
        unsigned long long win = s_red[0];
        if (tid < cnt && s_key[tid] == win) s_key[tid] = 0xFFFFFFFFFFFFFFFFull;
        if (tid == 0) {
            g_idx[b * KK + k] = (int)(win & 0xFFFFFFFFu);
            loss += (double)ord_f32((unsigned int)(win >> 32));
        }
        __syncthreads();
    }
    if (tid == 0) g_rowloss[b] = (float)loss;
}

// ---------------- deterministic loss reduction ----------------
__global__ __launch_bounds__(256)
void loss_reduce_kernel(float* __restrict__ out, int out_size) {
    __shared__ double s[256];
    int tid = threadIdx.x;
    double acc = 0.0;
    for (int i = tid; i < BB; i += 256) acc += (double)g_rowloss[i];
    s[tid] = acc;
    __syncthreads();
    for (int st = 128; st > 0; st >>= 1) {
        if (tid < st) s[tid] += s[tid + st];
        __syncthreads();
    }
    if (tid == 0) out[out_size - 1] = (float)(s[0] / (double)(BB * KK));
}

// ---------------- gather: out[b, k*L+l, :] = values[idx[b,k], l, :] ----------------
__global__ __launch_bounds__(256)
void gather_kernel(const float* __restrict__ values, float* __restrict__ out) {
    const long long total = (long long)BB * (KK * LL) * (DD / 4);   // 52,428,800 float4s
    long long gid = (long long)blockIdx.x * 256 + threadIdx.x;
    if (gid >= total) return;
    int b  = (int)(gid / 6400);
    int r  = (int)(gid % 6400);
    int j  = r >> 8;        // 0..24
    int d4 = r & 255;       // 0..255
    int k = j / LL;
    int l = j - k * LL;
    int p = g_idx[b * KK + k];
    float4 v = ((const float4*)values)[((size_t)p * LL + l) * (DD / 4) + d4];
    ((float4*)out)[gid] = v;
}

// ---------------- launch ----------------
extern "C" void kernel_launch(void* const* d_in, const int* in_sizes, int n_in,
                              void* d_out, int out_size) {
    const float* x      = (const float*)d_in[0];   // (B,1,D)
    const float* keys   = (const float*)d_in[1];   // (P,D)
    const float* values = (const float*)d_in[2];   // (P,L,D)
    float* out = (float*)d_out;

    norms_kernel<<<BB + PP, 256>>>(x, keys);
    split_x_kernel<<<BB, 256>>>(x);
    split_k_kernel<<<PP, 256>>>(keys);

    dim3 gg(PP / 128, BB / 128);   // (32, 64)
    gemm_mma_kernel<<<gg, 256>>>();

    topk_kernel<<<BB, 256>>>(x, keys);

    loss_reduce_kernel<<<1, 256>>>(out, out_size);

    const long long total4 = (long long)BB * (KK * LL) * (DD / 4);
    int gblocks = (int)((total4 + 255) / 256);
    gather_kernel<<<gblocks, 256>>>(values, out);
}

// round 7
// speedup vs baseline: 13.5653x; 1.1742x over previous
#include <cuda_runtime.h>
#include <cuda_bf16.h>
#include <math.h>
#include <stdint.h>

// Problem constants
#define BB 8192
#define PP 4096
#define DD 1024
#define LL 5
#define KK 5
#define EPSV 1e-8f

// Candidate margin (dist units). Pure-bf16 GEMM dist error ~5e-5 std,
// ~2.6e-4 max over all entries. DELTA = 4e-3 is a ~15-sigma guarantee.
#define DELTA 4e-3f
#define CMAX 128

// GEMM config (pure bf16, K = DD = 1024)
#define BKC 32               // k per chunk (bf16)
#define NCH (DD / BKC)       // 32 chunks
#define ROWB 80              // padded smem row bytes (64B data + 16B pad)
#define STAGE_BYTES (128 * ROWB * 2)   // A tile + B tile = 20480
#define NSTAGE 4

#define ULMAX 0xFFFFFFFFFFFFFFFFull

// ---------------- scratch (device globals: allocation-free) ----------------
__device__ float g_dot[(size_t)BB * PP];              // 128 MB approx scores
__device__ __nv_bfloat16 g_A[(size_t)BB * DD];        // 16 MB  bf16(x)
__device__ __nv_bfloat16 g_Bk[(size_t)PP * DD];       // 8 MB   bf16(keys)
__device__ float g_xn[BB];
__device__ float g_kn[PP];
__device__ float g_rowloss[BB];
__device__ int   g_idx[BB * KK];

// ================= helpers =================
__device__ __forceinline__ uint32_t smem_to_u32(const void* p) {
    uint32_t a;
    asm("{ .reg .u64 t; cvta.to.shared.u64 t, %1; cvt.u32.u64 %0, t; }" : "=r"(a) : "l"(p));
    return a;
}
__device__ __forceinline__ void cp16(uint32_t dst, const void* src) {
    asm volatile("cp.async.cg.shared.global [%0], [%1], 16;" :: "r"(dst), "l"(src) : "memory");
}
__device__ __forceinline__ void ldsm_x4(uint32_t (&r)[4], uint32_t addr) {
    asm volatile("ldmatrix.sync.aligned.m8n8.x4.shared.b16 {%0,%1,%2,%3}, [%4];"
        : "=r"(r[0]), "=r"(r[1]), "=r"(r[2]), "=r"(r[3]) : "r"(addr));
}
__device__ __forceinline__ void mma16816(float (&c)[4], const uint32_t (&a)[4],
                                         uint32_t b0, uint32_t b1) {
    asm volatile("mma.sync.aligned.m16n8k16.row.col.f32.bf16.bf16.f32 "
        "{%0,%1,%2,%3}, {%4,%5,%6,%7}, {%8,%9}, {%0,%1,%2,%3};"
        : "+f"(c[0]), "+f"(c[1]), "+f"(c[2]), "+f"(c[3])
        : "r"(a[0]), "r"(a[1]), "r"(a[2]), "r"(a[3]), "r"(b0), "r"(b1));
}

// ---------------- norms (double accumulation) + fused bf16 conversion ----------------
__global__ __launch_bounds__(256)
void norms_kernel(const float* __restrict__ x,
                  const float* __restrict__ keys) {
    int v = blockIdx.x;
    const float* src;
    float* dst;
    __nv_bfloat16* bfdst;
    if (v < BB) { src = x + (size_t)v * DD;           dst = &g_xn[v];      bfdst = g_A  + (size_t)v * DD; }
    else        { src = keys + (size_t)(v - BB) * DD; dst = &g_kn[v - BB]; bfdst = g_Bk + (size_t)(v - BB) * DD; }

    double acc = 0.0;
    for (int d = threadIdx.x; d < DD; d += 256) {
        float t = src[d];
        bfdst[d] = __float2bfloat16_rn(t);
        double td = (double)t;
        acc += td * td;
    }
    __shared__ double s[256];
    s[threadIdx.x] = acc;
    __syncthreads();
    for (int st = 128; st > 0; st >>= 1) {
        if (threadIdx.x < st) s[threadIdx.x] += s[threadIdx.x + st];
        __syncthreads();
    }
    if (threadIdx.x == 0) *dst = (float)sqrt(s[0]);
}

// ---------------- mma.sync bf16 GEMM: 128x128 tile, K=1024, 4-stage ----------------
// g_dot[m, n] = sum_k g_A[m, k] * g_Bk[n, k]
__global__ __launch_bounds__(256, 2)
void gemm_mma_kernel() {
    extern __shared__ __align__(16) char smem[];   // NSTAGE * STAGE_BYTES
    const uint32_t sb = smem_to_u32(smem);

    const int tid  = threadIdx.x;
    const int wid  = tid >> 5;
    const int lane = tid & 31;
    const int wm = wid >> 2;       // 0..1  -> M offset wm*64
    const int wn = wid & 3;        // 0..3  -> N offset wn*32
    const int bx = blockIdx.x;     // N tile: PP/128 = 32
    const int by = blockIdx.y;     // M tile: BB/128 = 64

    const __nv_bfloat16* Abase = g_A  + (size_t)(by * 128) * DD;
    const __nv_bfloat16* Bbase = g_Bk + (size_t)(bx * 128) * DD;

    // per-stage layout: A at +0 (128 rows x 80B), B at +10240 (128 rows x 80B)
    auto load_chunk = [&](int c, int st) {
        const uint32_t base = sb + st * STAGE_BYTES;
#pragma unroll
        for (int i = 0; i < 2; i++) {          // A: ids 0..511
            int id = tid + i * 256;
            int r = id >> 2, s = id & 3;
            cp16(base + r * ROWB + s * 16,
                 Abase + (size_t)r * DD + c * BKC + s * 8);
        }
#pragma unroll
        for (int i = 0; i < 2; i++) {          // B: ids 0..511
            int id = tid + i * 256;
            int r = id >> 2, s = id & 3;
            cp16(base + 10240 + r * ROWB + s * 16,
                 Bbase + (size_t)r * DD + c * BKC + s * 8);
        }
        asm volatile("cp.async.commit_group;" ::: "memory");
    };

    float acc[4][4][4];
#pragma unroll
    for (int i = 0; i < 4; i++)
#pragma unroll
        for (int j = 0; j < 4; j++)
#pragma unroll
            for (int q = 0; q < 4; q++) acc[i][j][q] = 0.f;

    load_chunk(0, 0);
    load_chunk(1, 1);
    load_chunk(2, 2);

    // ldmatrix source rows for this lane
    const int lr  = lane & 15;          // row within 16-row tile
    const int lkh = (lane >> 4) * 16;   // 0 or 16 bytes (k-half)

    for (int c = 0; c < NCH; c++) {
        const int st = c & (NSTAGE - 1);
        if      (c < NCH - 2) asm volatile("cp.async.wait_group 2;" ::: "memory");
        else if (c == NCH - 2) asm volatile("cp.async.wait_group 1;" ::: "memory");
        else                   asm volatile("cp.async.wait_group 0;" ::: "memory");
        __syncthreads();

        const uint32_t aB = sb + st * STAGE_BYTES;
        const uint32_t bB = aB + 10240;

#pragma unroll
        for (int ks = 0; ks < 2; ks++) {       // two k16 steps per 32-chunk
            const int kb = ks * 32;            // byte offset of k16 within row
            uint32_t a[4][4];
#pragma unroll
            for (int mi = 0; mi < 4; mi++)
                ldsm_x4(a[mi], aB + (wm * 64 + mi * 16 + lr) * ROWB + kb + lkh);
            uint32_t bt[2][4];
#pragma unroll
            for (int nt = 0; nt < 2; nt++)
                ldsm_x4(bt[nt], bB + (wn * 32 + nt * 16 + lr) * ROWB + kb + lkh);
#pragma unroll
            for (int mi = 0; mi < 4; mi++)
#pragma unroll
                for (int ni = 0; ni < 4; ni++) {
                    const int nt = ni >> 1, hi = ni & 1;
                    mma16816(acc[mi][ni], a[mi], bt[nt][hi], bt[nt][hi + 2]);
                }
        }
        if (c + 3 < NCH) load_chunk(c + 3, (c + 3) & (NSTAGE - 1));
    }

    // epilogue: direct float2 stores
    const int g  = lane >> 2;
    const int t2 = (lane & 3) * 2;
    const size_t rowbase = (size_t)(by * 128 + wm * 64);
    const int colbase = bx * 128 + wn * 32;
#pragma unroll
    for (int mi = 0; mi < 4; mi++)
#pragma unroll
        for (int ni = 0; ni < 4; ni++) {
            size_t r0 = rowbase + mi * 16 + g;
            int col = colbase + ni * 8 + t2;
            float2 v0 = make_float2(acc[mi][ni][0], acc[mi][ni][1]);
            float2 v1 = make_float2(acc[mi][ni][2], acc[mi][ni][3]);
            *(float2*)&g_dot[r0 * PP + col]       = v0;
            *(float2*)&g_dot[(r0 + 8) * PP + col] = v1;
        }
}

// ---------------- ordered-float helpers ----------------
__device__ __forceinline__ unsigned int f32_ord(float f) {
    unsigned int b = __float_as_uint(f);
    return b ^ ((b & 0x80000000u) ? 0xFFFFFFFFu : 0x80000000u);
}
__device__ __forceinline__ float ord_f32(unsigned int o) {
    unsigned int b = o ^ ((o & 0x80000000u) ? 0x80000000u : 0xFFFFFFFFu);
    return __uint_as_float(b);
}

// ---------------- top-5: per-thread top5 + margin + exact rescore ----------------
__global__ __launch_bounds__(256)
void topk_kernel(const float* __restrict__ x, const float* __restrict__ keys) {
    const int b = blockIdx.x;
    const int tid = threadIdx.x;
    const int lane = tid & 31;
    const int warp = tid >> 5;

    __shared__ unsigned int s_ord[PP];              // 16 KB approx dist (ordered)
    __shared__ float s_x[DD];                       // 4 KB row of x
    __shared__ unsigned long long s_cand[5 * 256];  // 10 KB per-thread top5
    __shared__ unsigned long long s_key[CMAX];      // candidates (ord<<32)|p
    __shared__ unsigned long long s_red[8];
    __shared__ int s_cnt;

    const float xnb = g_xn[b];
    const float4* drow4 = (const float4*)(g_dot + (size_t)b * PP);
    const float4* kn4   = (const float4*)g_kn;

    unsigned long long t5[5] = {ULMAX, ULMAX, ULMAX, ULMAX, ULMAX};
    auto ins = [&](unsigned long long key) {
        if (key < t5[4]) {
            t5[4] = key;
#pragma unroll
            for (int j = 4; j > 0; j--)
                if (t5[j] < t5[j - 1]) {
                    unsigned long long t = t5[j - 1]; t5[j - 1] = t5[j]; t5[j] = t;
                }
        }
    };
    auto proc = [&](int p, float dot, float kn) {
        float dist = 1.0f - __fdiv_rn(dot, fmaxf(xnb * kn, EPSV));
        unsigned int o = f32_ord(dist);
        s_ord[p] = o;
        ins(((unsigned long long)o << 32) | (unsigned int)p);
    };
#pragma unroll
    for (int i = 0; i < 4; i++) {
        int p4 = i * 256 + tid;
        float4 dv = drow4[p4];
        float4 kv = kn4[p4];
        int p0 = p4 * 4;
        proc(p0 + 0, dv.x, kv.x);
        proc(p0 + 1, dv.y, kv.y);
        proc(p0 + 2, dv.z, kv.z);
        proc(p0 + 3, dv.w, kv.w);
    }
    ((float4*)s_x)[tid] = ((const float4*)(x + (size_t)b * DD))[tid];
#pragma unroll
    for (int j = 0; j < 5; j++) s_cand[j * 256 + tid] = t5[j];
    if (tid == 0) s_cnt = KK;
    __syncthreads();

    // ---- 5 selection passes over 1280 reduced candidates ----
    unsigned int T_ord = 0;
    for (int k = 0; k < KK; k++) {
        unsigned long long best = s_cand[tid];
#pragma unroll
        for (int j = 1; j < 5; j++) best = min(best, s_cand[j * 256 + tid]);
#pragma unroll
        for (int st = 16; st > 0; st >>= 1)
            best = min(best, __shfl_xor_sync(0xFFFFFFFFu, best, st));
        if (lane == 0) s_red[warp] = best;
        __syncthreads();
        if (warp == 0) {
            unsigned long long v = (lane < 8) ? s_red[lane] : ULMAX;
#pragma unroll
            for (int st = 4; st > 0; st >>= 1)
                v = min(v, __shfl_xor_sync(0xFFFFFFFFu, v, st));
            if (lane == 0) s_red[0] = v;
        }
        __syncthreads();
        unsigned long long win = s_red[0];
#pragma unroll
        for (int j = 0; j < 5; j++)
            if (s_cand[j * 256 + tid] == win) s_cand[j * 256 + tid] = ULMAX;
        if (tid == 0) {
            s_key[k] = win;
            s_ord[(unsigned int)(win & 0xFFFFFFFFu)] = 0xFFFFFFFFu;
        }
        T_ord = (unsigned int)(win >> 32);
        __syncthreads();
    }

    // ---- margin scan: all remaining keys with dist <= T + DELTA ----
    const unsigned int th_ord = f32_ord(ord_f32(T_ord) + DELTA);
    for (int p = tid; p < PP; p += 256) {
        unsigned int o = s_ord[p];
        if (o <= th_ord) {
            int pos = atomicAdd(&s_cnt, 1);
            if (pos < CMAX)
                s_key[pos] = ((unsigned long long)o << 32) | (unsigned int)p;
        }
    }
    __syncthreads();
    const int cnt = min(s_cnt, CMAX);

    // ---- exact rescore: fp64 dot, fp32-quantized dist ----
    for (int c = warp; c < cnt; c += 8) {
        const int p = (int)(s_key[c] & 0xFFFFFFFFu);
        const float* krow = keys + (size_t)p * DD;
        double acc = 0.0;
        for (int d = lane; d < DD; d += 32)
            acc += (double)s_x[d] * (double)krow[d];
#pragma unroll
        for (int st = 16; st > 0; st >>= 1)
            acc += __shfl_xor_sync(0xFFFFFFFFu, acc, st);
        if (lane == 0) {
            float dotf  = (float)acc;
            float denom = fmaxf(xnb * g_kn[p], EPSV);
            float dist  = 1.0f - __fdiv_rn(dotf, denom);
            s_key[c] = ((unsigned long long)f32_ord(dist) << 32) | (unsigned int)p;
        }
    }
    __syncthreads();

    // ---- exact top-5 among candidates ----
    double loss = 0.0;
    for (int k = 0; k < KK; k++) {
        unsigned long long best = (tid < cnt) ? s_key[tid] : ULMAX;
#pragma unroll
        for (int st = 16; st > 0; st >>= 1)
            best = min(best, __shfl_xor_sync(0xFFFFFFFFu, best, st));
        if (lane == 0) s_red[warp] = best;
        __syncthreads();
        if (warp == 0) {
            unsigned long long v = (lane < 8) ? s_red[lane] : ULMAX;
#pragma unroll
            for (int st = 4; st > 0; st >>= 1)
                v = min(v, __shfl_xor_sync(0xFFFFFFFFu, v, st));
            if (lane == 0) s_red[0] = v;
        }
        __syncthreads();
        unsigned long long win = s_red[0];
        if (tid < cnt && s_key[tid] == win) s_key[tid] = ULMAX;
        if (tid == 0) {
            g_idx[b * KK + k] = (int)(win & 0xFFFFFFFFu);
            loss += (double)ord_f32((unsigned int)(win >> 32));
        }
        __syncthreads();
    }
    if (tid == 0) g_rowloss[b] = (float)loss;
}

// ---------------- deterministic loss reduction ----------------
__global__ __launch_bounds__(256)
void loss_reduce_kernel(float* __restrict__ out, int out_size) {
    __shared__ double s[256];
    int tid = threadIdx.x;
    double acc = 0.0;
    for (int i = tid; i < BB; i += 256) acc += (double)g_rowloss[i];
    s[tid] = acc;
    __syncthreads();
    for (int st = 128; st > 0; st >>= 1) {
        if (tid < st) s[tid] += s[tid + st];
        __syncthreads();
    }
    if (tid == 0) out[out_size - 1] = (float)(s[0] / (double)(BB * KK));
}

// ---------------- gather: out[b, k*L+l, :] = values[idx[b,k], l, :] ----------------
__global__ __launch_bounds__(256)
void gather_kernel(const float* __restrict__ values, float* __restrict__ out) {
    const long long total = (long long)BB * (KK * LL) * (DD / 4);   // 52,428,800 float4s
    long long gid = (long long)blockIdx.x * 256 + threadIdx.x;
    if (gid >= total) return;
    int b  = (int)(gid / 6400);
    int r  = (int)(gid % 6400);
    int j  = r >> 8;        // 0..24
    int d4 = r & 255;       // 0..255
    int k = j / LL;
    int l = j - k * LL;
    int p = g_idx[b * KK + k];
    float4 v = ((const float4*)values)[((size_t)p * LL + l) * (DD / 4) + d4];
    ((float4*)out)[gid] = v;
}

// ---------------- launch ----------------
extern "C" void kernel_launch(void* const* d_in, const int* in_sizes, int n_in,
                              void* d_out, int out_size) {
    const float* x      = (const float*)d_in[0];   // (B,1,D)
    const float* keys   = (const float*)d_in[1];   // (P,D)
    const float* values = (const float*)d_in[2];   // (P,L,D)
    float* out = (float*)d_out;

    cudaFuncSetAttribute(gemm_mma_kernel,
                         cudaFuncAttributeMaxDynamicSharedMemorySize,
                         NSTAGE * STAGE_BYTES);

    norms_kernel<<<BB + PP, 256>>>(x, keys);

    dim3 gg(PP / 128, BB / 128);   // (32, 64)
    gemm_mma_kernel<<<gg, 256, NSTAGE * STAGE_BYTES>>>();

    topk_kernel<<<BB, 256>>>(x, keys);

    loss_reduce_kernel<<<1, 256>>>(out, out_size);

    const long long total4 = (long long)BB * (KK * LL) * (DD / 4);
    int gblocks = (int)((total4 + 255) / 256);
    gather_kernel<<<gblocks, 256>>>(values, out);
}

// round 8
// speedup vs baseline: 13.6636x; 1.0072x over previous
#include <cuda_runtime.h>
#include <cuda_bf16.h>
#include <math.h>
#include <stdint.h>

// Problem constants
#define BB 8192
#define PP 4096
#define DD 1024
#define LL 5
#define KK 5
#define EPSV 1e-8f

// Candidate margin (dist units). Pure-bf16 GEMM dist error ~5e-5 std,
// ~2.6e-4 max over all entries. DELTA = 4e-3 is a ~15-sigma guarantee.
#define DELTA 4e-3f
#define CMAX 128

// GEMM config (pure bf16, K = DD = 1024)
#define BKC 32               // k per chunk (bf16)
#define NCH (DD / BKC)       // 32 chunks
#define ROWB 80              // padded smem row bytes (64B data + 16B pad)
#define STAGE_BYTES (128 * ROWB * 2)   // A tile + B tile = 20480
#define NSTAGE 4

#define ULMAX 0xFFFFFFFFFFFFFFFFull

// ---------------- scratch (device globals: allocation-free) ----------------
__device__ float g_dot[(size_t)BB * PP];              // 128 MB approx scores
__device__ __nv_bfloat16 g_A[(size_t)BB * DD];        // 16 MB  bf16(x)
__device__ __nv_bfloat16 g_Bk[(size_t)PP * DD];       // 8 MB   bf16(keys)
__device__ float g_xn[BB];
__device__ float g_kn[PP];
__device__ float g_ikn[PP];                            // 1/kn (approx ranking only)
__device__ float g_rowloss[BB];
__device__ int   g_idx[BB * KK];

// ================= helpers =================
__device__ __forceinline__ uint32_t smem_to_u32(const void* p) {
    uint32_t a;
    asm("{ .reg .u64 t; cvta.to.shared.u64 t, %1; cvt.u32.u64 %0, t; }" : "=r"(a) : "l"(p));
    return a;
}
__device__ __forceinline__ void cp16(uint32_t dst, const void* src) {
    asm volatile("cp.async.cg.shared.global [%0], [%1], 16;" :: "r"(dst), "l"(src) : "memory");
}
__device__ __forceinline__ void ldsm_x4(uint32_t (&r)[4], uint32_t addr) {
    asm volatile("ldmatrix.sync.aligned.m8n8.x4.shared.b16 {%0,%1,%2,%3}, [%4];"
        : "=r"(r[0]), "=r"(r[1]), "=r"(r[2]), "=r"(r[3]) : "r"(addr));
}
__device__ __forceinline__ void mma16816(float (&c)[4], const uint32_t (&a)[4],
                                         uint32_t b0, uint32_t b1) {
    asm volatile("mma.sync.aligned.m16n8k16.row.col.f32.bf16.bf16.f32 "
        "{%0,%1,%2,%3}, {%4,%5,%6,%7}, {%8,%9}, {%0,%1,%2,%3};"
        : "+f"(c[0]), "+f"(c[1]), "+f"(c[2]), "+f"(c[3])
        : "r"(a[0]), "r"(a[1]), "r"(a[2]), "r"(a[3]), "r"(b0), "r"(b1));
}

// ---------------- norms (double accumulation) + fused bf16 conversion ----------------
__global__ __launch_bounds__(256)
void norms_kernel(const float* __restrict__ x,
                  const float* __restrict__ keys) {
    int v = blockIdx.x;
    const float* src;
    __nv_bfloat16* bfdst;
    bool iskey = (v >= BB);
    if (!iskey) { src = x + (size_t)v * DD;           bfdst = g_A  + (size_t)v * DD; }
    else        { src = keys + (size_t)(v - BB) * DD; bfdst = g_Bk + (size_t)(v - BB) * DD; }

    double acc = 0.0;
    for (int d = threadIdx.x; d < DD; d += 256) {
        float t = src[d];
        bfdst[d] = __float2bfloat16_rn(t);
        double td = (double)t;
        acc += td * td;
    }
    __shared__ double s[256];
    s[threadIdx.x] = acc;
    __syncthreads();
    for (int st = 128; st > 0; st >>= 1) {
        if (threadIdx.x < st) s[threadIdx.x] += s[threadIdx.x + st];
        __syncthreads();
    }
    if (threadIdx.x == 0) {
        float n = (float)sqrt(s[0]);
        if (!iskey) g_xn[v] = n;
        else {
            g_kn[v - BB]  = n;
            g_ikn[v - BB] = 1.0f / fmaxf(n, 1e-30f);
        }
    }
}

// ---------------- mma.sync bf16 GEMM: 128x128 tile, K=1024, 4-stage ----------------
__global__ __launch_bounds__(256, 2)
void gemm_mma_kernel() {
    extern __shared__ __align__(16) char smem[];   // NSTAGE * STAGE_BYTES
    const uint32_t sb = smem_to_u32(smem);

    const int tid  = threadIdx.x;
    const int wid  = tid >> 5;
    const int lane = tid & 31;
    const int wm = wid >> 2;
    const int wn = wid & 3;
    const int bx = blockIdx.x;     // N tile: PP/128 = 32
    const int by = blockIdx.y;     // M tile: BB/128 = 64

    const __nv_bfloat16* Abase = g_A  + (size_t)(by * 128) * DD;
    const __nv_bfloat16* Bbase = g_Bk + (size_t)(bx * 128) * DD;

    auto load_chunk = [&](int c, int st) {
        const uint32_t base = sb + st * STAGE_BYTES;
#pragma unroll
        for (int i = 0; i < 2; i++) {
            int id = tid + i * 256;
            int r = id >> 2, s = id & 3;
            cp16(base + r * ROWB + s * 16,
                 Abase + (size_t)r * DD + c * BKC + s * 8);
        }
#pragma unroll
        for (int i = 0; i < 2; i++) {
            int id = tid + i * 256;
            int r = id >> 2, s = id & 3;
            cp16(base + 10240 + r * ROWB + s * 16,
                 Bbase + (size_t)r * DD + c * BKC + s * 8);
        }
        asm volatile("cp.async.commit_group;" ::: "memory");
    };

    float acc[4][4][4];
#pragma unroll
    for (int i = 0; i < 4; i++)
#pragma unroll
        for (int j = 0; j < 4; j++)
#pragma unroll
            for (int q = 0; q < 4; q++) acc[i][j][q] = 0.f;

    load_chunk(0, 0);
    load_chunk(1, 1);
    load_chunk(2, 2);

    const int lr  = lane & 15;
    const int lkh = (lane >> 4) * 16;

    for (int c = 0; c < NCH; c++) {
        const int st = c & (NSTAGE - 1);
        if      (c < NCH - 2)  asm volatile("cp.async.wait_group 2;" ::: "memory");
        else if (c == NCH - 2) asm volatile("cp.async.wait_group 1;" ::: "memory");
        else                   asm volatile("cp.async.wait_group 0;" ::: "memory");
        __syncthreads();

        const uint32_t aB = sb + st * STAGE_BYTES;
        const uint32_t bB = aB + 10240;

#pragma unroll
        for (int ks = 0; ks < 2; ks++) {
            const int kb = ks * 32;
            uint32_t a[4][4];
#pragma unroll
            for (int mi = 0; mi < 4; mi++)
                ldsm_x4(a[mi], aB + (wm * 64 + mi * 16 + lr) * ROWB + kb + lkh);
            uint32_t bt[2][4];
#pragma unroll
            for (int nt = 0; nt < 2; nt++)
                ldsm_x4(bt[nt], bB + (wn * 32 + nt * 16 + lr) * ROWB + kb + lkh);
#pragma unroll
            for (int mi = 0; mi < 4; mi++)
#pragma unroll
                for (int ni = 0; ni < 4; ni++) {
                    const int nt = ni >> 1, hi = ni & 1;
                    mma16816(acc[mi][ni], a[mi], bt[nt][hi], bt[nt][hi + 2]);
                }
        }
        if (c + 3 < NCH) load_chunk(c + 3, (c + 3) & (NSTAGE - 1));
    }

    const int g  = lane >> 2;
    const int t2 = (lane & 3) * 2;
    const size_t rowbase = (size_t)(by * 128 + wm * 64);
    const int colbase = bx * 128 + wn * 32;
#pragma unroll
    for (int mi = 0; mi < 4; mi++)
#pragma unroll
        for (int ni = 0; ni < 4; ni++) {
            size_t r0 = rowbase + mi * 16 + g;
            int col = colbase + ni * 8 + t2;
            float2 v0 = make_float2(acc[mi][ni][0], acc[mi][ni][1]);
            float2 v1 = make_float2(acc[mi][ni][2], acc[mi][ni][3]);
            *(float2*)&g_dot[r0 * PP + col]       = v0;
            *(float2*)&g_dot[(r0 + 8) * PP + col] = v1;
        }
}

// ---------------- ordered-float helpers ----------------
__device__ __forceinline__ unsigned int f32_ord(float f) {
    unsigned int b = __float_as_uint(f);
    return b ^ ((b & 0x80000000u) ? 0xFFFFFFFFu : 0x80000000u);
}
__device__ __forceinline__ float ord_f32(unsigned int o) {
    unsigned int b = o ^ ((o & 0x80000000u) ? 0x80000000u : 0xFFFFFFFFu);
    return __uint_as_float(b);
}

// ---------------- top-5: multiply-only approx score + margin + exact rescore ----------------
// Approx ranking by score = dot * (1/kn)  (descending == dist ascending, since
// xn is a positive per-row constant). No divisions in the 4096-entry scan.
__global__ __launch_bounds__(256)
void topk_kernel(const float* __restrict__ x, const float* __restrict__ keys) {
    const int b = blockIdx.x;
    const int tid = threadIdx.x;
    const int lane = tid & 31;
    const int warp = tid >> 5;

    __shared__ float s_score[PP];                   // 16 KB approx scores
    __shared__ float s_x[DD];                       // 4 KB row of x
    __shared__ unsigned long long s_cand[5 * 256];  // 10 KB per-thread top5
    __shared__ unsigned long long s_key[CMAX];
    __shared__ unsigned long long s_red[8];
    __shared__ int s_cnt;

    const float xnb = g_xn[b];
    const float4* drow4 = (const float4*)(g_dot + (size_t)b * PP);
    const float4* ik4   = (const float4*)g_ikn;

    // per-thread top5 of (ord(-score), p) — smallest key == largest score
    unsigned long long t5[5] = {ULMAX, ULMAX, ULMAX, ULMAX, ULMAX};
    auto ins = [&](unsigned long long key) {
        if (key < t5[4]) {
            t5[4] = key;
#pragma unroll
            for (int j = 4; j > 0; j--)
                if (t5[j] < t5[j - 1]) {
                    unsigned long long t = t5[j - 1]; t5[j - 1] = t5[j]; t5[j] = t;
                }
        }
    };
    auto proc = [&](int p, float dot, float ikn) {
        float score = dot * ikn;
        s_score[p] = score;
        ins(((unsigned long long)f32_ord(-score) << 32) | (unsigned int)p);
    };
#pragma unroll
    for (int i = 0; i < 4; i++) {
        int p4 = i * 256 + tid;
        float4 dv = drow4[p4];
        float4 kv = ik4[p4];
        int p0 = p4 * 4;
        proc(p0 + 0, dv.x, kv.x);
        proc(p0 + 1, dv.y, kv.y);
        proc(p0 + 2, dv.z, kv.z);
        proc(p0 + 3, dv.w, kv.w);
    }
    ((float4*)s_x)[tid] = ((const float4*)(x + (size_t)b * DD))[tid];
#pragma unroll
    for (int j = 0; j < 5; j++) s_cand[j * 256 + tid] = t5[j];
    if (tid == 0) s_cnt = 0;
    __syncthreads();

    // ---- find 5th-largest approx score (5 passes over 1280 reduced cands) ----
    unsigned long long win = ULMAX;
    for (int k = 0; k < KK; k++) {
        unsigned long long best = s_cand[tid];
#pragma unroll
        for (int j = 1; j < 5; j++) best = min(best, s_cand[j * 256 + tid]);
#pragma unroll
        for (int st = 16; st > 0; st >>= 1)
            best = min(best, __shfl_xor_sync(0xFFFFFFFFu, best, st));
        if (lane == 0) s_red[warp] = best;
        __syncthreads();
        if (warp == 0) {
            unsigned long long v = (lane < 8) ? s_red[lane] : ULMAX;
#pragma unroll
            for (int st = 4; st > 0; st >>= 1)
                v = min(v, __shfl_xor_sync(0xFFFFFFFFu, v, st));
            if (lane == 0) s_red[0] = v;
        }
        __syncthreads();
        win = s_red[0];
#pragma unroll
        for (int j = 0; j < 5; j++)
            if (s_cand[j * 256 + tid] == win) s_cand[j * 256 + tid] = ULMAX;
        __syncthreads();
    }
    const float score5 = -ord_f32((unsigned int)(win >> 32));
    const float th = score5 - DELTA * xnb;   // margin in score units

    // ---- collect all candidates with score >= th ----
#pragma unroll
    for (int i = 0; i < 16; i++) {
        int p = i * 256 + tid;
        if (s_score[p] >= th) {
            int pos = atomicAdd(&s_cnt, 1);
            if (pos < CMAX) s_key[pos] = (unsigned long long)(unsigned int)p;
        }
    }
    __syncthreads();
    const int cnt = min(s_cnt, CMAX);

    // ---- exact rescore: fp64 dot, fp32-quantized dist (matches reference) ----
    for (int c = warp; c < cnt; c += 8) {
        const int p = (int)(s_key[c] & 0xFFFFFFFFu);
        const float* krow = keys + (size_t)p * DD;
        double acc = 0.0;
        for (int d = lane; d < DD; d += 32)
            acc += (double)s_x[d] * (double)krow[d];
#pragma unroll
        for (int st = 16; st > 0; st >>= 1)
            acc += __shfl_xor_sync(0xFFFFFFFFu, acc, st);
        if (lane == 0) {
            float dotf  = (float)acc;
            float denom = fmaxf(xnb * g_kn[p], EPSV);
            float dist  = 1.0f - __fdiv_rn(dotf, denom);
            s_key[c] = ((unsigned long long)f32_ord(dist) << 32) | (unsigned int)p;
        }
    }
    __syncthreads();

    // ---- exact top-5 among candidates (ties -> lowest index, like jax) ----
    double loss = 0.0;
    for (int k = 0; k < KK; k++) {
        unsigned long long best = (tid < cnt) ? s_key[tid] : ULMAX;
#pragma unroll
        for (int st = 16; st > 0; st >>= 1)
            best = min(best, __shfl_xor_sync(0xFFFFFFFFu, best, st));
        if (lane == 0) s_red[warp] = best;
        __syncthreads();
        if (warp == 0) {
            unsigned long long v = (lane < 8) ? s_red[lane] : ULMAX;
#pragma unroll
            for (int st = 4; st > 0; st >>= 1)
                v = min(v, __shfl_xor_sync(0xFFFFFFFFu, v, st));
            if (lane == 0) s_red[0] = v;
        }
        __syncthreads();
        unsigned long long w2 = s_red[0];
        if (tid < cnt && s_key[tid] == w2) s_key[tid] = ULMAX;
        if (tid == 0) {
            g_idx[b * KK + k] = (int)(w2 & 0xFFFFFFFFu);
            loss += (double)ord_f32((unsigned int)(w2 >> 32));
        }
        __syncthreads();
    }
    if (tid == 0) g_rowloss[b] = (float)loss;
}

// ---------------- deterministic loss reduction ----------------
__global__ __launch_bounds__(256)
void loss_reduce_kernel(float* __restrict__ out, int out_size) {
    __shared__ double s[256];
    int tid = threadIdx.x;
    double acc = 0.0;
    for (int i = tid; i < BB; i += 256) acc += (double)g_rowloss[i];
    s[tid] = acc;
    __syncthreads();
    for (int st = 128; st > 0; st >>= 1) {
        if (tid < st) s[tid] += s[tid + st];
        __syncthreads();
    }
    if (tid == 0) out[out_size - 1] = (float)(s[0] / (double)(BB * KK));
}

// ---------------- gather: out[b, k*L+l, :] = values[idx[b,k], l, :] ----------------
__global__ __launch_bounds__(256)
void gather_kernel(const float* __restrict__ values, float* __restrict__ out) {
    const long long total = (long long)BB * (KK * LL) * (DD / 4);   // 52,428,800 float4s
    long long gid = (long long)blockIdx.x * 256 + threadIdx.x;
    if (gid >= total) return;
    int b  = (int)(gid / 6400);
    int r  = (int)(gid % 6400);
    int j  = r >> 8;        // 0..24
    int d4 = r & 255;       // 0..255
    int k = j / LL;
    int l = j - k * LL;
    int p = g_idx[b * KK + k];
    float4 v = __ldg(&((const float4*)values)[((size_t)p * LL + l) * (DD / 4) + d4]);
    __stcs(&((float4*)out)[gid], v);   // streaming store: don't pollute L2
}

// ---------------- launch ----------------
extern "C" void kernel_launch(void* const* d_in, const int* in_sizes, int n_in,
                              void* d_out, int out_size) {
    const float* x      = (const float*)d_in[0];   // (B,1,D)
    const float* keys   = (const float*)d_in[1];   // (P,D)
    const float* values = (const float*)d_in[2];   // (P,L,D)
    float* out = (float*)d_out;

    cudaFuncSetAttribute(gemm_mma_kernel,
                         cudaFuncAttributeMaxDynamicSharedMemorySize,
                         NSTAGE * STAGE_BYTES);

    norms_kernel<<<BB + PP, 256>>>(x, keys);

    dim3 gg(PP / 128, BB / 128);   // (32, 64)
    gemm_mma_kernel<<<gg, 256, NSTAGE * STAGE_BYTES>>>();

    topk_kernel<<<BB, 256>>>(x, keys);

    loss_reduce_kernel<<<1, 256>>>(out, out_size);

    const long long total4 = (long long)BB * (KK * LL) * (DD / 4);
    int gblocks = (int)((total4 + 255) / 256);
    gather_kernel<<<gblocks, 256>>>(values, out);
}

// round 9
// speedup vs baseline: 14.2633x; 1.0439x over previous
#include <cuda_runtime.h>
#include <cuda_bf16.h>
#include <math.h>
#include <stdint.h>

// Problem constants
#define BB 8192
#define PP 4096
#define DD 1024
#define LL 5
#define KK 5
#define EPSV 1e-8f

// Candidate margin (dist units). Pure-bf16 GEMM dist error ~5e-5 std,
// ~2.6e-4 max. DELTA = 4e-3 is a ~15-sigma guarantee.
#define DELTA 4e-3f
#define CMAX 128

// GEMM config (pure bf16, K = DD = 1024)
#define BKC 32               // k per chunk (bf16)
#define NCH (DD / BKC)       // 32 chunks
#define ROWB 80              // padded smem row bytes (64B data + 16B pad)
#define STAGE_BYTES (128 * ROWB * 2)   // A tile + B tile = 20480
#define NSTAGE 4
#define GEMM_SMEM (NSTAGE * STAGE_BYTES)   // 81920; epilogue reuses 67584

#define ULMAX 0xFFFFFFFFFFFFFFFFull

// ---------------- scratch (device globals: allocation-free) ----------------
__device__ float g_dot[(size_t)BB * PP];              // 128 MB approx SCORES (dot/kn)
__device__ __nv_bfloat16 g_A[(size_t)BB * DD];        // 16 MB  bf16(x)
__device__ __nv_bfloat16 g_Bk[(size_t)PP * DD];       // 8 MB   bf16(keys)
__device__ float g_xn[BB];
__device__ float g_kn[PP];
__device__ float g_ikn[PP];                            // 1/kn (approx ranking only)
__device__ float g_rowloss[BB];
__device__ int   g_idx[BB * KK];

// ================= helpers =================
__device__ __forceinline__ uint32_t smem_to_u32(const void* p) {
    uint32_t a;
    asm("{ .reg .u64 t; cvta.to.shared.u64 t, %1; cvt.u32.u64 %0, t; }" : "=r"(a) : "l"(p));
    return a;
}
__device__ __forceinline__ void cp16(uint32_t dst, const void* src) {
    asm volatile("cp.async.cg.shared.global [%0], [%1], 16;" :: "r"(dst), "l"(src) : "memory");
}
__device__ __forceinline__ void ldsm_x4(uint32_t (&r)[4], uint32_t addr) {
    asm volatile("ldmatrix.sync.aligned.m8n8.x4.shared.b16 {%0,%1,%2,%3}, [%4];"
        : "=r"(r[0]), "=r"(r[1]), "=r"(r[2]), "=r"(r[3]) : "r"(addr));
}
__device__ __forceinline__ void mma16816(float (&c)[4], const uint32_t (&a)[4],
                                         uint32_t b0, uint32_t b1) {
    asm volatile("mma.sync.aligned.m16n8k16.row.col.f32.bf16.bf16.f32 "
        "{%0,%1,%2,%3}, {%4,%5,%6,%7}, {%8,%9}, {%0,%1,%2,%3};"
        : "+f"(c[0]), "+f"(c[1]), "+f"(c[2]), "+f"(c[3])
        : "r"(a[0]), "r"(a[1]), "r"(a[2]), "r"(a[3]), "r"(b0), "r"(b1));
}

// ---------------- norms (double accumulation) + fused bf16 conversion ----------------
__global__ __launch_bounds__(256)
void norms_kernel(const float* __restrict__ x,
                  const float* __restrict__ keys) {
    int v = blockIdx.x;
    const float* src;
    __nv_bfloat16* bfdst;
    bool iskey = (v >= BB);
    if (!iskey) { src = x + (size_t)v * DD;           bfdst = g_A  + (size_t)v * DD; }
    else        { src = keys + (size_t)(v - BB) * DD; bfdst = g_Bk + (size_t)(v - BB) * DD; }

    double acc = 0.0;
    for (int d = threadIdx.x; d < DD; d += 256) {
        float t = src[d];
        bfdst[d] = __float2bfloat16_rn(t);
        double td = (double)t;
        acc += td * td;
    }
    __shared__ double s[256];
    s[threadIdx.x] = acc;
    __syncthreads();
    for (int st = 128; st > 0; st >>= 1) {
        if (threadIdx.x < st) s[threadIdx.x] += s[threadIdx.x + st];
        __syncthreads();
    }
    if (threadIdx.x == 0) {
        float n = (float)sqrt(s[0]);
        if (!iskey) g_xn[v] = n;
        else {
            g_kn[v - BB]  = n;
            g_ikn[v - BB] = 1.0f / fmaxf(n, 1e-30f);
        }
    }
}

// ---------------- mma.sync bf16 GEMM: 128x128 tile, K=1024, 4-stage ----------------
// writes SCORES: g_dot[m, n] = (sum_k A[m,k]*B[n,k]) * (1/kn[n])
__global__ __launch_bounds__(256, 2)
void gemm_mma_kernel() {
    extern __shared__ __align__(16) char smem[];   // GEMM_SMEM
    const uint32_t sb = smem_to_u32(smem);

    const int tid  = threadIdx.x;
    const int wid  = tid >> 5;
    const int lane = tid & 31;
    const int wm = wid >> 2;
    const int wn = wid & 3;
    const int bx = blockIdx.x;     // N tile: PP/128 = 32
    const int by = blockIdx.y;     // M tile: BB/128 = 64

    const __nv_bfloat16* Abase = g_A  + (size_t)(by * 128) * DD;
    const __nv_bfloat16* Bbase = g_Bk + (size_t)(bx * 128) * DD;

    auto load_chunk = [&](int c, int st) {
        const uint32_t base = sb + st * STAGE_BYTES;
#pragma unroll
        for (int i = 0; i < 2; i++) {
            int id = tid + i * 256;
            int r = id >> 2, s = id & 3;
            cp16(base + r * ROWB + s * 16,
                 Abase + (size_t)r * DD + c * BKC + s * 8);
        }
#pragma unroll
        for (int i = 0; i < 2; i++) {
            int id = tid + i * 256;
            int r = id >> 2, s = id & 3;
            cp16(base + 10240 + r * ROWB + s * 16,
                 Bbase + (size_t)r * DD + c * BKC + s * 8);
        }
        asm volatile("cp.async.commit_group;" ::: "memory");
    };

    float acc[4][4][4];
#pragma unroll
    for (int i = 0; i < 4; i++)
#pragma unroll
        for (int j = 0; j < 4; j++)
#pragma unroll
            for (int q = 0; q < 4; q++) acc[i][j][q] = 0.f;

    load_chunk(0, 0);
    load_chunk(1, 1);
    load_chunk(2, 2);

    const int lr  = lane & 15;
    const int lkh = (lane >> 4) * 16;

    for (int c = 0; c < NCH; c++) {
        const int st = c & (NSTAGE - 1);
        if      (c < NCH - 2)  asm volatile("cp.async.wait_group 2;" ::: "memory");
        else if (c == NCH - 2) asm volatile("cp.async.wait_group 1;" ::: "memory");
        else                   asm volatile("cp.async.wait_group 0;" ::: "memory");
        __syncthreads();

        const uint32_t aB = sb + st * STAGE_BYTES;
        const uint32_t bB = aB + 10240;

#pragma unroll
        for (int ks = 0; ks < 2; ks++) {
            const int kb = ks * 32;
            uint32_t a[4][4];
#pragma unroll
            for (int mi = 0; mi < 4; mi++)
                ldsm_x4(a[mi], aB + (wm * 64 + mi * 16 + lr) * ROWB + kb + lkh);
            uint32_t bt[2][4];
#pragma unroll
            for (int nt = 0; nt < 2; nt++)
                ldsm_x4(bt[nt], bB + (wn * 32 + nt * 16 + lr) * ROWB + kb + lkh);
#pragma unroll
            for (int mi = 0; mi < 4; mi++)
#pragma unroll
                for (int ni = 0; ni < 4; ni++) {
                    const int nt = ni >> 1, hi = ni & 1;
                    mma16816(acc[mi][ni], a[mi], bt[nt][hi], bt[nt][hi + 2]);
                }
        }
        if (c + 3 < NCH) load_chunk(c + 3, (c + 3) & (NSTAGE - 1));
    }

    // ---- epilogue: smem transpose (132-float padded rows) + coalesced stores,
    //      fused score multiply by 1/kn ----
    __syncthreads();                    // all warps done reading stage smem
    float* sf = (float*)smem;           // 128 x 132 floats = 67584 B <= GEMM_SMEM
    const int g  = lane >> 2;
    const int t2 = (lane & 3) * 2;
#pragma unroll
    for (int mi = 0; mi < 4; mi++)
#pragma unroll
        for (int ni = 0; ni < 4; ni++) {
            int r0 = wm * 64 + mi * 16 + g;
            int c0 = wn * 32 + ni * 8 + t2;
            sf[r0 * 132 + c0]           = acc[mi][ni][0];
            sf[r0 * 132 + c0 + 1]       = acc[mi][ni][1];
            sf[(r0 + 8) * 132 + c0]     = acc[mi][ni][2];
            sf[(r0 + 8) * 132 + c0 + 1] = acc[mi][ni][3];
        }
    __syncthreads();
    const float4* ikn4 = ((const float4*)g_ikn) + bx * 32;
    float* obase = g_dot + (size_t)(by * 128) * PP + bx * 128;
#pragma unroll
    for (int i = 0; i < 16; i++) {
        int idx = tid + i * 256;
        int r = idx >> 5, c4 = idx & 31;
        float4 v = ((const float4*)sf)[r * 33 + c4];
        float4 s = ikn4[c4];
        v.x *= s.x; v.y *= s.y; v.z *= s.z; v.w *= s.w;
        ((float4*)(obase + (size_t)r * PP))[c4] = v;
    }
}

// ---------------- ordered-float helpers ----------------
__device__ __forceinline__ unsigned int f32_ord(float f) {
    unsigned int b = __float_as_uint(f);
    return b ^ ((b & 0x80000000u) ? 0xFFFFFFFFu : 0x80000000u);
}
__device__ __forceinline__ float ord_f32(unsigned int o) {
    unsigned int b = o ^ ((o & 0x80000000u) ? 0x80000000u : 0xFFFFFFFFu);
    return __uint_as_float(b);
}

// ---------------- top-5: approx scores + margin + exact rescore ----------------
__global__ __launch_bounds__(256)
void topk_kernel(const float* __restrict__ x, const float* __restrict__ keys) {
    const int b = blockIdx.x;
    const int tid = threadIdx.x;
    const int lane = tid & 31;
    const int warp = tid >> 5;

    __shared__ float s_score[PP];                   // 16 KB approx scores
    __shared__ float s_x[DD];                       // 4 KB row of x
    __shared__ unsigned long long s_cand[5 * 256];  // 10 KB per-thread top5
    __shared__ unsigned long long s_key[CMAX];
    __shared__ unsigned long long s_red[8];
    __shared__ int s_cnt;

    const float xnb = g_xn[b];
    const float4* drow4 = (const float4*)(g_dot + (size_t)b * PP);

    // per-thread top5 of (ord(-score), p) — smallest key == largest score
    unsigned long long t5[5] = {ULMAX, ULMAX, ULMAX, ULMAX, ULMAX};
    auto ins = [&](unsigned long long key) {
        if (key < t5[4]) {
            t5[4] = key;
#pragma unroll
            for (int j = 4; j > 0; j--)
                if (t5[j] < t5[j - 1]) {
                    unsigned long long t = t5[j - 1]; t5[j - 1] = t5[j]; t5[j] = t;
                }
        }
    };
    auto proc = [&](int p, float score) {
        s_score[p] = score;
        ins(((unsigned long long)f32_ord(-score) << 32) | (unsigned int)p);
    };
#pragma unroll
    for (int i = 0; i < 4; i++) {
        int p4 = i * 256 + tid;
        float4 dv = drow4[p4];
        int p0 = p4 * 4;
        proc(p0 + 0, dv.x);
        proc(p0 + 1, dv.y);
        proc(p0 + 2, dv.z);
        proc(p0 + 3, dv.w);
    }
    ((float4*)s_x)[tid] = ((const float4*)(x + (size_t)b * DD))[tid];
#pragma unroll
    for (int j = 0; j < 5; j++) s_cand[j * 256 + tid] = t5[j];
    if (tid == 0) s_cnt = 0;
    __syncthreads();

    // ---- find 5th-largest approx score (5 passes over 1280 reduced cands) ----
    unsigned long long win = ULMAX;
    for (int k = 0; k < KK; k++) {
        unsigned long long best = s_cand[tid];
#pragma unroll
        for (int j = 1; j < 5; j++) best = min(best, s_cand[j * 256 + tid]);
#pragma unroll
        for (int st = 16; st > 0; st >>= 1)
            best = min(best, __shfl_xor_sync(0xFFFFFFFFu, best, st));
        if (lane == 0) s_red[warp] = best;
        __syncthreads();
        if (warp == 0) {
            unsigned long long v = (lane < 8) ? s_red[lane] : ULMAX;
#pragma unroll
            for (int st = 4; st > 0; st >>= 1)
                v = min(v, __shfl_xor_sync(0xFFFFFFFFu, v, st));
            if (lane == 0) s_red[0] = v;
        }
        __syncthreads();
        win = s_red[0];
#pragma unroll
        for (int j = 0; j < 5; j++)
            if (s_cand[j * 256 + tid] == win) s_cand[j * 256 + tid] = ULMAX;
        __syncthreads();
    }
    const float score5 = -ord_f32((unsigned int)(win >> 32));
    const float th = score5 - DELTA * xnb;   // margin in score units

    // ---- collect all candidates with score >= th ----
#pragma unroll
    for (int i = 0; i < 16; i++) {
        int p = i * 256 + tid;
        if (s_score[p] >= th) {
            int pos = atomicAdd(&s_cnt, 1);
            if (pos < CMAX) s_key[pos] = (unsigned long long)(unsigned int)p;
        }
    }
    __syncthreads();
    const int cnt = min(s_cnt, CMAX);

    // ---- exact rescore: fp64 dot, fp32-quantized dist (matches reference) ----
    for (int c = warp; c < cnt; c += 8) {
        const int p = (int)(s_key[c] & 0xFFFFFFFFu);
        const float* krow = keys + (size_t)p * DD;
        double acc = 0.0;
        for (int d = lane; d < DD; d += 32)
            acc += (double)s_x[d] * (double)krow[d];
#pragma unroll
        for (int st = 16; st > 0; st >>= 1)
            acc += __shfl_xor_sync(0xFFFFFFFFu, acc, st);
        if (lane == 0) {
            float dotf  = (float)acc;
            float denom = fmaxf(xnb * g_kn[p], EPSV);
            float dist  = 1.0f - __fdiv_rn(dotf, denom);
            s_key[c] = ((unsigned long long)f32_ord(dist) << 32) | (unsigned int)p;
        }
    }
    __syncthreads();

    // ---- exact top-5 among candidates (ties -> lowest index, like jax) ----
    double loss = 0.0;
    for (int k = 0; k < KK; k++) {
        unsigned long long best = (tid < cnt) ? s_key[tid] : ULMAX;
#pragma unroll
        for (int st = 16; st > 0; st >>= 1)
            best = min(best, __shfl_xor_sync(0xFFFFFFFFu, best, st));
        if (lane == 0) s_red[warp] = best;
        __syncthreads();
        if (warp == 0) {
            unsigned long long v = (lane < 8) ? s_red[lane] : ULMAX;
#pragma unroll
            for (int st = 4; st > 0; st >>= 1)
                v = min(v, __shfl_xor_sync(0xFFFFFFFFu, v, st));
            if (lane == 0) s_red[0] = v;
        }
        __syncthreads();
        unsigned long long w2 = s_red[0];
        if (tid < cnt && s_key[tid] == w2) s_key[tid] = ULMAX;
        if (tid == 0) {
            g_idx[b * KK + k] = (int)(w2 & 0xFFFFFFFFu);
            loss += (double)ord_f32((unsigned int)(w2 >> 32));
        }
        __syncthreads();
    }
    if (tid == 0) g_rowloss[b] = (float)loss;
}

// ---------------- gather: one block per (b,k); copy 5 rows of 4KB ----------------
__global__ __launch_bounds__(256)
void gather_kernel(const float* __restrict__ values, float* __restrict__ out) {
    const int bk = blockIdx.x;            // 0 .. BB*KK-1
    const int tid = threadIdx.x;
    const int p = g_idx[bk];
    const float4* src = (const float4*)(values + (size_t)p  * (LL * DD));
    float4*       dst = (float4*)(out    + (size_t)bk * (LL * DD));
#pragma unroll
    for (int i = 0; i < 5; i++) {
        float4 v = __ldg(&src[i * 256 + tid]);
        __stcs(&dst[i * 256 + tid], v);
    }
}

// ---------------- deterministic loss reduction ----------------
__global__ __launch_bounds__(256)
void loss_reduce_kernel(float* __restrict__ out, int out_size) {
    __shared__ double s[256];
    int tid = threadIdx.x;
    double acc = 0.0;
    for (int i = tid; i < BB; i += 256) acc += (double)g_rowloss[i];
    s[tid] = acc;
    __syncthreads();
    for (int st = 128; st > 0; st >>= 1) {
        if (tid < st) s[tid] += s[tid + st];
        __syncthreads();
    }
    if (tid == 0) out[out_size - 1] = (float)(s[0] / (double)(BB * KK));
}

// ---------------- launch ----------------
extern "C" void kernel_launch(void* const* d_in, const int* in_sizes, int n_in,
                              void* d_out, int out_size) {
    const float* x      = (const float*)d_in[0];   // (B,1,D)
    const float* keys   = (const float*)d_in[1];   // (P,D)
    const float* values = (const float*)d_in[2];   // (P,L,D)
    float* out = (float*)d_out;

    cudaFuncSetAttribute(gemm_mma_kernel,
                         cudaFuncAttributeMaxDynamicSharedMemorySize, GEMM_SMEM);

    norms_kernel<<<BB + PP, 256>>>(x, keys);                 // #1

    dim3 gg(PP / 128, BB / 128);                             // (32, 64)
    gemm_mma_kernel<<<gg, 256, GEMM_SMEM>>>();               // #2

    topk_kernel<<<BB, 256>>>(x, keys);                       // #3

    gather_kernel<<<BB * KK, 256>>>(values, out);            // #4  <- ncu slot

    loss_reduce_kernel<<<1, 256>>>(out, out_size);           // #5
}

// round 10
// speedup vs baseline: 14.2792x; 1.0011x over previous
#include <cuda_runtime.h>
#include <cuda_bf16.h>
#include <math.h>
#include <stdint.h>

// Problem constants
#define BB 8192
#define PP 4096
#define DD 1024
#define LL 5
#define KK 5
#define EPSV 1e-8f

// Candidate margin (dist units). Pure-bf16 GEMM dist error ~5e-5 std,
// ~2.6e-4 max. DELTA = 4e-3 is a ~15-sigma guarantee.
#define DELTA 4e-3f
#define CMAX 128

// GEMM config (pure bf16, K = DD = 1024)
#define BKC 32               // k per chunk (bf16)
#define NCH (DD / BKC)       // 32 chunks
#define ROWB 80              // padded smem row bytes (64B data + 16B pad)
#define STAGE_BYTES (128 * ROWB * 2)   // A tile + B tile = 20480
#define NSTAGE 4
#define GEMM_SMEM (NSTAGE * STAGE_BYTES)   // 81920; epilogue reuses 67584

#define ULMAX 0xFFFFFFFFFFFFFFFFull

// ---------------- scratch (device globals: allocation-free) ----------------
__device__ float g_dot[(size_t)BB * PP];              // 128 MB approx SCORES (dot/kn)
__device__ __nv_bfloat16 g_A[(size_t)BB * DD];        // 16 MB  bf16(x)
__device__ __nv_bfloat16 g_Bk[(size_t)PP * DD];       // 8 MB   bf16(keys)
__device__ float g_xn[BB];
__device__ float g_kn[PP];
__device__ float g_ikn[PP];                            // 1/kn (approx ranking only)
__device__ float g_rowloss[BB];
__device__ int   g_idx[BB * KK];

// ================= helpers =================
__device__ __forceinline__ uint32_t smem_to_u32(const void* p) {
    uint32_t a;
    asm("{ .reg .u64 t; cvta.to.shared.u64 t, %1; cvt.u32.u64 %0, t; }" : "=r"(a) : "l"(p));
    return a;
}
__device__ __forceinline__ void cp16(uint32_t dst, const void* src) {
    asm volatile("cp.async.cg.shared.global [%0], [%1], 16;" :: "r"(dst), "l"(src) : "memory");
}
__device__ __forceinline__ void ldsm_x4(uint32_t (&r)[4], uint32_t addr) {
    asm volatile("ldmatrix.sync.aligned.m8n8.x4.shared.b16 {%0,%1,%2,%3}, [%4];"
        : "=r"(r[0]), "=r"(r[1]), "=r"(r[2]), "=r"(r[3]) : "r"(addr));
}
__device__ __forceinline__ void mma16816(float (&c)[4], const uint32_t (&a)[4],
                                         uint32_t b0, uint32_t b1) {
    asm volatile("mma.sync.aligned.m16n8k16.row.col.f32.bf16.bf16.f32 "
        "{%0,%1,%2,%3}, {%4,%5,%6,%7}, {%8,%9}, {%0,%1,%2,%3};"
        : "+f"(c[0]), "+f"(c[1]), "+f"(c[2]), "+f"(c[3])
        : "r"(a[0]), "r"(a[1]), "r"(a[2]), "r"(a[3]), "r"(b0), "r"(b1));
}

// ---------------- norms (double accumulation) + fused bf16 conversion ----------------
__global__ __launch_bounds__(256)
void norms_x_kernel(const float* __restrict__ x) {
    int v = blockIdx.x;
    const float* src = x + (size_t)v * DD;
    __nv_bfloat16* bfdst = g_A + (size_t)v * DD;

    double acc = 0.0;
    for (int d = threadIdx.x; d < DD; d += 256) {
        float t = src[d];
        bfdst[d] = __float2bfloat16_rn(t);
        double td = (double)t;
        acc += td * td;
    }
    __shared__ double s[256];
    s[threadIdx.x] = acc;
    __syncthreads();
    for (int st = 128; st > 0; st >>= 1) {
        if (threadIdx.x < st) s[threadIdx.x] += s[threadIdx.x + st];
        __syncthreads();
    }
    if (threadIdx.x == 0) g_xn[v] = (float)sqrt(s[0]);
}

__global__ __launch_bounds__(256)
void norms_k_kernel(const float* __restrict__ keys) {
    int v = blockIdx.x;
    const float* src = keys + (size_t)v * DD;
    __nv_bfloat16* bfdst = g_Bk + (size_t)v * DD;

    double acc = 0.0;
    for (int d = threadIdx.x; d < DD; d += 256) {
        float t = src[d];
        bfdst[d] = __float2bfloat16_rn(t);
        double td = (double)t;
        acc += td * td;
    }
    __shared__ double s[256];
    s[threadIdx.x] = acc;
    __syncthreads();
    for (int st = 128; st > 0; st >>= 1) {
        if (threadIdx.x < st) s[threadIdx.x] += s[threadIdx.x + st];
        __syncthreads();
    }
    if (threadIdx.x == 0) {
        float n = (float)sqrt(s[0]);
        g_kn[v]  = n;
        g_ikn[v] = 1.0f / fmaxf(n, 1e-30f);
    }
}

// ---------------- mma.sync bf16 GEMM: 128x128 tile, K=1024, 4-stage ----------------
// writes SCORES: g_dot[m, n] = (sum_k A[m,k]*B[n,k]) * (1/kn[n])
__global__ __launch_bounds__(256, 2)
void gemm_mma_kernel() {
    extern __shared__ __align__(16) char smem[];   // GEMM_SMEM
    const uint32_t sb = smem_to_u32(smem);

    const int tid  = threadIdx.x;
    const int wid  = tid >> 5;
    const int lane = tid & 31;
    const int wm = wid >> 2;
    const int wn = wid & 3;
    const int bx = blockIdx.x;     // N tile: PP/128 = 32
    const int by = blockIdx.y;     // M tile: BB/128 = 64

    const __nv_bfloat16* Abase = g_A  + (size_t)(by * 128) * DD;
    const __nv_bfloat16* Bbase = g_Bk + (size_t)(bx * 128) * DD;

    auto load_chunk = [&](int c, int st) {
        const uint32_t base = sb + st * STAGE_BYTES;
#pragma unroll
        for (int i = 0; i < 2; i++) {
            int id = tid + i * 256;
            int r = id >> 2, s = id & 3;
            cp16(base + r * ROWB + s * 16,
                 Abase + (size_t)r * DD + c * BKC + s * 8);
        }
#pragma unroll
        for (int i = 0; i < 2; i++) {
            int id = tid + i * 256;
            int r = id >> 2, s = id & 3;
            cp16(base + 10240 + r * ROWB + s * 16,
                 Bbase + (size_t)r * DD + c * BKC + s * 8);
        }
        asm volatile("cp.async.commit_group;" ::: "memory");
    };

    float acc[4][4][4];
#pragma unroll
    for (int i = 0; i < 4; i++)
#pragma unroll
        for (int j = 0; j < 4; j++)
#pragma unroll
            for (int q = 0; q < 4; q++) acc[i][j][q] = 0.f;

    load_chunk(0, 0);
    load_chunk(1, 1);
    load_chunk(2, 2);

    const int lr  = lane & 15;
    const int lkh = (lane >> 4) * 16;

    for (int c = 0; c < NCH; c++) {
        const int st = c & (NSTAGE - 1);
        if      (c < NCH - 2)  asm volatile("cp.async.wait_group 2;" ::: "memory");
        else if (c == NCH - 2) asm volatile("cp.async.wait_group 1;" ::: "memory");
        else                   asm volatile("cp.async.wait_group 0;" ::: "memory");
        __syncthreads();

        const uint32_t aB = sb + st * STAGE_BYTES;
        const uint32_t bB = aB + 10240;

#pragma unroll
        for (int ks = 0; ks < 2; ks++) {
            const int kb = ks * 32;
            uint32_t a[4][4];
#pragma unroll
            for (int mi = 0; mi < 4; mi++)
                ldsm_x4(a[mi], aB + (wm * 64 + mi * 16 + lr) * ROWB + kb + lkh);
            uint32_t bt[2][4];
#pragma unroll
            for (int nt = 0; nt < 2; nt++)
                ldsm_x4(bt[nt], bB + (wn * 32 + nt * 16 + lr) * ROWB + kb + lkh);
#pragma unroll
            for (int mi = 0; mi < 4; mi++)
#pragma unroll
                for (int ni = 0; ni < 4; ni++) {
                    const int nt = ni >> 1, hi = ni & 1;
                    mma16816(acc[mi][ni], a[mi], bt[nt][hi], bt[nt][hi + 2]);
                }
        }
        if (c + 3 < NCH) load_chunk(c + 3, (c + 3) & (NSTAGE - 1));
    }

    // ---- epilogue: smem transpose (132-float padded rows) + coalesced stores,
    //      fused score multiply by 1/kn ----
    __syncthreads();
    float* sf = (float*)smem;           // 128 x 132 floats = 67584 B <= GEMM_SMEM
    const int g  = lane >> 2;
    const int t2 = (lane & 3) * 2;
#pragma unroll
    for (int mi = 0; mi < 4; mi++)
#pragma unroll
        for (int ni = 0; ni < 4; ni++) {
            int r0 = wm * 64 + mi * 16 + g;
            int c0 = wn * 32 + ni * 8 + t2;
            sf[r0 * 132 + c0]           = acc[mi][ni][0];
            sf[r0 * 132 + c0 + 1]       = acc[mi][ni][1];
            sf[(r0 + 8) * 132 + c0]     = acc[mi][ni][2];
            sf[(r0 + 8) * 132 + c0 + 1] = acc[mi][ni][3];
        }
    __syncthreads();
    const float4* ikn4 = ((const float4*)g_ikn) + bx * 32;
    float* obase = g_dot + (size_t)(by * 128) * PP + bx * 128;
#pragma unroll
    for (int i = 0; i < 16; i++) {
        int idx = tid + i * 256;
        int r = idx >> 5, c4 = idx & 31;
        float4 v = ((const float4*)sf)[r * 33 + c4];
        float4 s = ikn4[c4];
        v.x *= s.x; v.y *= s.y; v.z *= s.z; v.w *= s.w;
        ((float4*)(obase + (size_t)r * PP))[c4] = v;
    }
}

// ---------------- ordered-float helpers ----------------
__device__ __forceinline__ unsigned int f32_ord(float f) {
    unsigned int b = __float_as_uint(f);
    return b ^ ((b & 0x80000000u) ? 0xFFFFFFFFu : 0x80000000u);
}
__device__ __forceinline__ float ord_f32(unsigned int o) {
    unsigned int b = o ^ ((o & 0x80000000u) ? 0x80000000u : 0xFFFFFFFFu);
    return __uint_as_float(b);
}

// ---------------- top-5: approx scores + margin + exact rescore ----------------
__global__ __launch_bounds__(256)
void topk_kernel(const float* __restrict__ x, const float* __restrict__ keys) {
    const int b = blockIdx.x;
    const int tid = threadIdx.x;
    const int lane = tid & 31;
    const int warp = tid >> 5;

    __shared__ float s_x[DD];                       // 4 KB row of x
    __shared__ unsigned long long s_cand[5 * 256];  // 10 KB per-thread top5
    __shared__ unsigned long long s_key[CMAX];
    __shared__ unsigned long long s_red[8];
    __shared__ int s_cnt;

    const float xnb = g_xn[b];
    const float4* drow4 = (const float4*)(g_dot + (size_t)b * PP);

    // scores stay in registers; per-thread top5 of (ord(-score), p)
    float sc[16];
    unsigned long long t5[5] = {ULMAX, ULMAX, ULMAX, ULMAX, ULMAX};
    auto ins = [&](unsigned long long key) {
        if (key < t5[4]) {
            t5[4] = key;
#pragma unroll
            for (int j = 4; j > 0; j--)
                if (t5[j] < t5[j - 1]) {
                    unsigned long long t = t5[j - 1]; t5[j - 1] = t5[j]; t5[j] = t;
                }
        }
    };
#pragma unroll
    for (int i = 0; i < 4; i++) {
        int p4 = i * 256 + tid;
        float4 dv = drow4[p4];
        int p0 = p4 * 4;
        sc[i * 4 + 0] = dv.x; sc[i * 4 + 1] = dv.y;
        sc[i * 4 + 2] = dv.z; sc[i * 4 + 3] = dv.w;
        ins(((unsigned long long)f32_ord(-dv.x) << 32) | (unsigned int)(p0 + 0));
        ins(((unsigned long long)f32_ord(-dv.y) << 32) | (unsigned int)(p0 + 1));
        ins(((unsigned long long)f32_ord(-dv.z) << 32) | (unsigned int)(p0 + 2));
        ins(((unsigned long long)f32_ord(-dv.w) << 32) | (unsigned int)(p0 + 3));
    }
    ((float4*)s_x)[tid] = ((const float4*)(x + (size_t)b * DD))[tid];
#pragma unroll
    for (int j = 0; j < 5; j++) s_cand[j * 256 + tid] = t5[j];
    if (tid == 0) s_cnt = 0;
    __syncthreads();

    // ---- find 5th-largest approx score (5 passes over 1280 reduced cands) ----
    unsigned long long win = ULMAX;
    for (int k = 0; k < KK; k++) {
        unsigned long long best = s_cand[tid];
#pragma unroll
        for (int j = 1; j < 5; j++) best = min(best, s_cand[j * 256 + tid]);
#pragma unroll
        for (int st = 16; st > 0; st >>= 1)
            best = min(best, __shfl_xor_sync(0xFFFFFFFFu, best, st));
        if (lane == 0) s_red[warp] = best;
        __syncthreads();
        if (warp == 0) {
            unsigned long long v = (lane < 8) ? s_red[lane] : ULMAX;
#pragma unroll
            for (int st = 4; st > 0; st >>= 1)
                v = min(v, __shfl_xor_sync(0xFFFFFFFFu, v, st));
            if (lane == 0) s_red[0] = v;
        }
        __syncthreads();
        win = s_red[0];
#pragma unroll
        for (int j = 0; j < 5; j++)
            if (s_cand[j * 256 + tid] == win) s_cand[j * 256 + tid] = ULMAX;
        __syncthreads();
    }
    const float score5 = -ord_f32((unsigned int)(win >> 32));
    const float th = score5 - DELTA * xnb;   // margin in score units

    // ---- collect all candidates with score >= th (registers, no smem) ----
#pragma unroll
    for (int i = 0; i < 16; i++) {
        if (sc[i] >= th) {
            int p = (i & 3) + ((i >> 2) * 256 + tid) * 4;   // inverse of load map
            int pos = atomicAdd(&s_cnt, 1);
            if (pos < CMAX) s_key[pos] = (unsigned long long)(unsigned int)p;
        }
    }
    __syncthreads();
    const int cnt = min(s_cnt, CMAX);

    // ---- exact rescore: fp64 dot, fp32-quantized dist (matches reference) ----
    for (int c = warp; c < cnt; c += 8) {
        const int p = (int)(s_key[c] & 0xFFFFFFFFu);
        const float* krow = keys + (size_t)p * DD;
        double acc = 0.0;
        for (int d = lane; d < DD; d += 32)
            acc += (double)s_x[d] * (double)krow[d];
#pragma unroll
        for (int st = 16; st > 0; st >>= 1)
            acc += __shfl_xor_sync(0xFFFFFFFFu, acc, st);
        if (lane == 0) {
            float dotf  = (float)acc;
            float denom = fmaxf(xnb * g_kn[p], EPSV);
            float dist  = 1.0f - __fdiv_rn(dotf, denom);
            s_key[c] = ((unsigned long long)f32_ord(dist) << 32) | (unsigned int)p;
        }
    }
    __syncthreads();

    // ---- exact top-5 among candidates (ties -> lowest index, like jax) ----
    double loss = 0.0;
    for (int k = 0; k < KK; k++) {
        unsigned long long best = (tid < cnt) ? s_key[tid] : ULMAX;
#pragma unroll
        for (int st = 16; st > 0; st >>= 1)
            best = min(best, __shfl_xor_sync(0xFFFFFFFFu, best, st));
        if (lane == 0) s_red[warp] = best;
        __syncthreads();
        if (warp == 0) {
            unsigned long long v = (lane < 8) ? s_red[lane] : ULMAX;
#pragma unroll
            for (int st = 4; st > 0; st >>= 1)
                v = min(v, __shfl_xor_sync(0xFFFFFFFFu, v, st));
            if (lane == 0) s_red[0] = v;
        }
        __syncthreads();
        unsigned long long w2 = s_red[0];
        if (tid < cnt && s_key[tid] == w2) s_key[tid] = ULMAX;
        if (tid == 0) {
            g_idx[b * KK + k] = (int)(w2 & 0xFFFFFFFFu);
            loss += (double)ord_f32((unsigned int)(w2 >> 32));
        }
        __syncthreads();
    }
    if (tid == 0) g_rowloss[b] = (float)loss;
}

// ---------------- gather: one block per (b,k); copy 5 rows of 4KB ----------------
__global__ __launch_bounds__(256)
void gather_kernel(const float* __restrict__ values, float* __restrict__ out) {
    const int bk = blockIdx.x;            // 0 .. BB*KK-1
    const int tid = threadIdx.x;
    const int p = g_idx[bk];
    const float4* src = (const float4*)(values + (size_t)p  * (LL * DD));
    float4*       dst = (float4*)(out    + (size_t)bk * (LL * DD));
#pragma unroll
    for (int i = 0; i < 5; i++) {
        float4 v = __ldg(&src[i * 256 + tid]);
        __stcs(&dst[i * 256 + tid], v);
    }
}

// ---------------- deterministic loss reduction ----------------
__global__ __launch_bounds__(256)
void loss_reduce_kernel(float* __restrict__ out, int out_size) {
    __shared__ double s[256];
    int tid = threadIdx.x;
    double acc = 0.0;
    for (int i = tid; i < BB; i += 256) acc += (double)g_rowloss[i];
    s[tid] = acc;
    __syncthreads();
    for (int st = 128; st > 0; st >>= 1) {
        if (tid < st) s[tid] += s[tid + st];
        __syncthreads();
    }
    if (tid == 0) out[out_size - 1] = (float)(s[0] / (double)(BB * KK));
}

// ---------------- launch ----------------
extern "C" void kernel_launch(void* const* d_in, const int* in_sizes, int n_in,
                              void* d_out, int out_size) {
    const float* x      = (const float*)d_in[0];   // (B,1,D)
    const float* keys   = (const float*)d_in[1];   // (P,D)
    const float* values = (const float*)d_in[2];   // (P,L,D)
    float* out = (float*)d_out;

    cudaFuncSetAttribute(gemm_mma_kernel,
                         cudaFuncAttributeMaxDynamicSharedMemorySize, GEMM_SMEM);

    norms_x_kernel<<<BB, 256>>>(x);                          // #1
    norms_k_kernel<<<PP, 256>>>(keys);                       // #2

    dim3 gg(PP / 128, BB / 128);                             // (32, 64)
    gemm_mma_kernel<<<gg, 256, GEMM_SMEM>>>();               // #3

    topk_kernel<<<BB, 256>>>(x, keys);                       // #4  <- ncu slot

    gather_kernel<<<BB * KK, 256>>>(values, out);            // #5

    loss_reduce_kernel<<<1, 256>>>(out, out_size);           // #6
}